// round 10
// baseline (speedup 1.0000x reference)
#include <cuda_runtime.h>
#include <cuda_bf16.h>

// ---------------------------------------------------------------------------
// AbsPosAttention: out = softmax((x Wq * s + pos + relb) (x Wk)^T) (x Wv) Wo + bo
// B=2, N=2048, DIM=1536, H=8, dk=64, dv=192
// ---------------------------------------------------------------------------

typedef unsigned long long u64t;

#define BATCH 2
#define NSEQ  2048
#define DIMM  1536
#define HEADS 8
#define DK    64
#define DV    192
#define QSCALE 0.125f   // 64^-0.5

#define MROWS (BATCH*NSEQ)          // 4096
#define QKW   (HEADS*DK)            // 512
#define VW    (HEADS*DV)            // 1536

// scratch (static device arrays: allocation-free)
__device__ float g_q[MROWS * QKW];
__device__ float g_k[MROWS * QKW];
__device__ float g_v[MROWS * VW];
__device__ float g_ao[MROWS * VW];

// ---- packed f32x2 helpers (full-rate fp32 on sm_103a) ----
__device__ __forceinline__ u64t pack2(float x, float y) {
    u64t r; asm("mov.b64 %0, {%1, %2};" : "=l"(r) : "f"(x), "f"(y)); return r;
}
__device__ __forceinline__ void fma2(u64t& d, u64t a, u64t b) {
    asm("fma.rn.f32x2 %0, %1, %2, %0;" : "+l"(d) : "l"(a), "l"(b));
}
__device__ __forceinline__ void mul2(u64t& d, u64t a, u64t b) {
    asm("mul.rn.f32x2 %0, %1, %2;" : "=l"(d) : "l"(a), "l"(b));
}

// ---------------------------------------------------------------------------
// SGEMM: C[M,N] = A[M,K] @ B[K,N] (+bias). 128x128x16 tile, 256 thr, 8x8/thr.
// M,N multiples of 128; K multiple of 16.
// ---------------------------------------------------------------------------
__global__ __launch_bounds__(256, 2)
void sgemm128(const float* __restrict__ A, const float* __restrict__ Bm,
              float* __restrict__ C, const float* __restrict__ bias,
              int M, int N, int K)
{
    __shared__ float As[16][132];   // [k][row], padded to break store conflicts
    __shared__ float Bs[16][128];   // [k][col]

    const int tid  = threadIdx.x;
    const int tc   = tid & 15;
    const int tr   = tid >> 4;
    const int brow = blockIdx.y * 128;
    const int bcol = blockIdx.x * 128;

    float4 pa[2], pb[2];
    #pragma unroll
    for (int l = 0; l < 2; l++) {
        int e = tid + l * 256;
        pa[l] = *(const float4*)(A + (size_t)(brow + (e >> 2)) * K + ((e & 3) << 2));
        pb[l] = *(const float4*)(Bm + (size_t)(e >> 5) * N + bcol + ((e & 31) << 2));
    }

    u64t acc[8][4];
    #pragma unroll
    for (int i = 0; i < 8; i++)
        #pragma unroll
        for (int j = 0; j < 4; j++) acc[i][j] = 0ull;

    for (int k0 = 0; k0 < K; k0 += 16) {
        #pragma unroll
        for (int l = 0; l < 2; l++) {
            int e = tid + l * 256;
            int ar = e >> 2, ak = (e & 3) << 2;
            As[ak + 0][ar] = pa[l].x; As[ak + 1][ar] = pa[l].y;
            As[ak + 2][ar] = pa[l].z; As[ak + 3][ar] = pa[l].w;
            *(float4*)(&Bs[e >> 5][(e & 31) << 2]) = pb[l];
        }
        __syncthreads();
        if (k0 + 16 < K) {
            #pragma unroll
            for (int l = 0; l < 2; l++) {
                int e = tid + l * 256;
                pa[l] = *(const float4*)(A + (size_t)(brow + (e >> 2)) * K + k0 + 16 + ((e & 3) << 2));
                pb[l] = *(const float4*)(Bm + (size_t)(k0 + 16 + (e >> 5)) * N + bcol + ((e & 31) << 2));
            }
        }
        #pragma unroll
        for (int kk = 0; kk < 16; kk++) {
            float a[8];
            *(float4*)(a)     = *(const float4*)(&As[kk][tr * 8]);
            *(float4*)(a + 4) = *(const float4*)(&As[kk][tr * 8 + 4]);
            const u64t* bp = (const u64t*)(&Bs[kk][tc * 8]);
            u64t b0 = bp[0], b1 = bp[1], b2 = bp[2], b3 = bp[3];
            #pragma unroll
            for (int i = 0; i < 8; i++) {
                u64t ad = pack2(a[i], a[i]);
                fma2(acc[i][0], ad, b0);
                fma2(acc[i][1], ad, b1);
                fma2(acc[i][2], ad, b2);
                fma2(acc[i][3], ad, b3);
            }
        }
        __syncthreads();
    }

    #pragma unroll
    for (int i = 0; i < 8; i++) {
        int row = brow + tr * 8 + i;
        float o8[8];
        #pragma unroll
        for (int j = 0; j < 4; j++) {
            float2 f = *(float2*)&acc[i][j];
            o8[2 * j] = f.x; o8[2 * j + 1] = f.y;
        }
        if (bias) {
            #pragma unroll
            for (int j = 0; j < 8; j++) o8[j] += bias[bcol + tc * 8 + j];
        }
        float* cp = C + (size_t)row * N + bcol + tc * 8;
        *(float4*)(cp)     = *(float4*)(o8);
        *(float4*)(cp + 4) = *(float4*)(o8 + 4);
    }
}

// ---------------------------------------------------------------------------
// Flash attention (fp32, online softmax). Block = (b, h, 64-query tile).
// q/k layout [B,N,H*dk], v/out layout [B,N,H*dv]. Q gets SCALE + biases here.
// ---------------------------------------------------------------------------
#define QROW 68
#define VROW 196

__global__ __launch_bounds__(256, 2)
void attn_kernel(const float* __restrict__ qp, const float* __restrict__ kp,
                 const float* __restrict__ vp, const float* __restrict__ pos,
                 const float* __restrict__ relb, float* __restrict__ out)
{
    extern __shared__ float smf[];
    float* Qs   = smf;                 // 64 x QROW
    float* Ps   = Qs + 64 * QROW;      // K tile, then reused as P tile
    float* Vs   = Ps + 64 * QROW;      // 64 x VROW
    float* mrow = Vs + 64 * VROW;      // 64
    float* lrow = mrow + 64;           // 64
    float* srow = lrow + 64;           // 64 (rescale factor)

    const int tid = threadIdx.x;
    const int tx  = tid & 15, ty = tid >> 4;
    const int r0  = ty * 4;            // 4 query rows per thread
    const int c0  = tx * 12;           // 12 dv cols per thread
    const int b   = blockIdx.z, h = blockIdx.y;
    const int q0  = blockIdx.x * 64;

    const float* qb = qp + (size_t)b * NSEQ * QKW + h * DK;
    const float* kb = kp + (size_t)b * NSEQ * QKW + h * DK;
    const float* vb = vp + (size_t)b * NSEQ * VW  + h * DV;
    const float* pb = pos + (size_t)h * NSEQ * DK;

    // load Q tile with scale + pos_embed + rel_content_bias
    #pragma unroll
    for (int l = 0; l < 4; l++) {
        int e = tid + l * 256;           // 1024 float4s
        int r = e >> 4, d = (e & 15) << 2;
        float4 qv = *(const float4*)(qb + (size_t)(q0 + r) * QKW + d);
        float4 pv = *(const float4*)(pb + (size_t)(q0 + r) * DK + d);
        float4 rv = *(const float4*)(relb + h * DK + d);
        float4 o4;
        o4.x = qv.x * QSCALE + pv.x + rv.x;
        o4.y = qv.y * QSCALE + pv.y + rv.y;
        o4.z = qv.z * QSCALE + pv.z + rv.z;
        o4.w = qv.w * QSCALE + pv.w + rv.w;
        *(float4*)(Qs + r * QROW + d) = o4;
    }
    if (tid < 64) { mrow[tid] = -1e30f; lrow[tid] = 0.0f; }

    u64t oacc[4][6];
    #pragma unroll
    for (int i = 0; i < 4; i++)
        #pragma unroll
        for (int c = 0; c < 6; c++) oacc[i][c] = 0ull;

    for (int j0 = 0; j0 < NSEQ; j0 += 64) {
        __syncthreads();   // previous tile's P/V fully consumed
        // K tile -> Ps
        #pragma unroll
        for (int l = 0; l < 4; l++) {
            int e = tid + l * 256;
            int r = e >> 4, d = (e & 15) << 2;
            *(float4*)(Ps + r * QROW + d) =
                *(const float4*)(kb + (size_t)(j0 + r) * QKW + d);
        }
        // V tile -> Vs
        #pragma unroll
        for (int l = 0; l < 12; l++) {
            int e = tid + l * 256;       // 3072 float4s
            int r = e / 48, c = (e % 48) << 2;
            *(float4*)(Vs + r * VROW + c) =
                *(const float4*)(vb + (size_t)(j0 + r) * VW + c);
        }
        __syncthreads();

        // S = Q K^T : 4 rows x 4 cols per thread (cols tx, tx+16, tx+32, tx+48)
        float s[4][4];
        #pragma unroll
        for (int i = 0; i < 4; i++)
            #pragma unroll
            for (int j = 0; j < 4; j++) s[i][j] = 0.0f;
        #pragma unroll
        for (int d = 0; d < DK; d += 4) {
            float4 q4[4], k4[4];
            #pragma unroll
            for (int i = 0; i < 4; i++) q4[i] = *(const float4*)(Qs + (r0 + i) * QROW + d);
            #pragma unroll
            for (int j = 0; j < 4; j++) k4[j] = *(const float4*)(Ps + (tx + 16 * j) * QROW + d);
            #pragma unroll
            for (int i = 0; i < 4; i++)
                #pragma unroll
                for (int j = 0; j < 4; j++) {
                    s[i][j] = fmaf(q4[i].x, k4[j].x, s[i][j]);
                    s[i][j] = fmaf(q4[i].y, k4[j].y, s[i][j]);
                    s[i][j] = fmaf(q4[i].z, k4[j].z, s[i][j]);
                    s[i][j] = fmaf(q4[i].w, k4[j].w, s[i][j]);
                }
        }

        // row max across the 16 tx lanes
        float rm[4];
        #pragma unroll
        for (int i = 0; i < 4; i++) {
            rm[i] = fmaxf(fmaxf(s[i][0], s[i][1]), fmaxf(s[i][2], s[i][3]));
            #pragma unroll
            for (int o = 8; o > 0; o >>= 1)
                rm[i] = fmaxf(rm[i], __shfl_xor_sync(0xffffffffu, rm[i], o));
        }
        if (tx == 0) {
            #pragma unroll
            for (int i = 0; i < 4; i++) {
                float mo = mrow[r0 + i];
                float mn = fmaxf(mo, rm[i]);
                srow[r0 + i] = __expf(mo - mn);
                mrow[r0 + i] = mn;
            }
        }
        __syncthreads();   // stats visible; Ps (K) reads done -> safe to overwrite with P

        float rs[4];
        #pragma unroll
        for (int i = 0; i < 4; i++) {
            float mi = mrow[r0 + i];
            float p0 = __expf(s[i][0] - mi);
            float p1 = __expf(s[i][1] - mi);
            float p2 = __expf(s[i][2] - mi);
            float p3 = __expf(s[i][3] - mi);
            float* pr = Ps + (r0 + i) * QROW;
            pr[tx] = p0; pr[tx + 16] = p1; pr[tx + 32] = p2; pr[tx + 48] = p3;
            rs[i] = (p0 + p1) + (p2 + p3);
            #pragma unroll
            for (int o = 8; o > 0; o >>= 1)
                rs[i] += __shfl_xor_sync(0xffffffffu, rs[i], o);
        }
        if (tx == 0) {
            #pragma unroll
            for (int i = 0; i < 4; i++)
                lrow[r0 + i] = lrow[r0 + i] * srow[r0 + i] + rs[i];
        }
        __syncthreads();   // P + scale visible

        // rescale accumulators, then O += P @ V  (f32x2 packed)
        #pragma unroll
        for (int i = 0; i < 4; i++) {
            float sc = srow[r0 + i];
            u64t sd = pack2(sc, sc);
            #pragma unroll
            for (int c = 0; c < 6; c++) mul2(oacc[i][c], oacc[i][c], sd);
        }
        #pragma unroll 4
        for (int j4 = 0; j4 < 64; j4 += 4) {
            float4 p4[4];
            #pragma unroll
            for (int i = 0; i < 4; i++)
                p4[i] = *(const float4*)(Ps + (r0 + i) * QROW + j4);
            #pragma unroll
            for (int sj = 0; sj < 4; sj++) {
                const u64t* vr = (const u64t*)(Vs + (size_t)(j4 + sj) * VROW + c0);
                u64t v0 = vr[0], v1 = vr[1], v2 = vr[2], v3 = vr[3], v4 = vr[4], v5 = vr[5];
                #pragma unroll
                for (int i = 0; i < 4; i++) {
                    float pv = (sj == 0) ? p4[i].x : (sj == 1) ? p4[i].y
                             : (sj == 2) ? p4[i].z : p4[i].w;
                    u64t pd = pack2(pv, pv);
                    fma2(oacc[i][0], pd, v0);
                    fma2(oacc[i][1], pd, v1);
                    fma2(oacc[i][2], pd, v2);
                    fma2(oacc[i][3], pd, v3);
                    fma2(oacc[i][4], pd, v4);
                    fma2(oacc[i][5], pd, v5);
                }
            }
        }
    }

    // epilogue: divide by l, write [B,N,H*dv]
    #pragma unroll
    for (int i = 0; i < 4; i++) {
        float inv = 1.0f / lrow[r0 + i];
        float res[12];
        #pragma unroll
        for (int c = 0; c < 6; c++) {
            float2 f = *(float2*)&oacc[i][c];
            res[2 * c]     = f.x * inv;
            res[2 * c + 1] = f.y * inv;
        }
        float* ob = out + (size_t)(b * NSEQ + q0 + r0 + i) * VW + h * DV + c0;
        *(float4*)(ob)     = *(float4*)(res);
        *(float4*)(ob + 4) = *(float4*)(res + 4);
        *(float4*)(ob + 8) = *(float4*)(res + 8);
    }
}

// ---------------------------------------------------------------------------
extern "C" void kernel_launch(void* const* d_in, const int* in_sizes, int n_in,
                              void* d_out, int out_size)
{
    (void)in_sizes; (void)n_in; (void)out_size;
    const float* x   = (const float*)d_in[0];
    const float* Wq  = (const float*)d_in[1];
    const float* Wk  = (const float*)d_in[2];
    const float* Wv  = (const float*)d_in[3];
    const float* Wo  = (const float*)d_in[4];
    const float* bo  = (const float*)d_in[5];
    const float* pos = (const float*)d_in[6];
    const float* rb  = (const float*)d_in[7];
    float* out = (float*)d_out;

    float *gq, *gk, *gv, *gao;
    cudaGetSymbolAddress((void**)&gq,  g_q);
    cudaGetSymbolAddress((void**)&gk,  g_k);
    cudaGetSymbolAddress((void**)&gv,  g_v);
    cudaGetSymbolAddress((void**)&gao, g_ao);

    const int attn_smem = (64 * QROW * 2 + 64 * VROW + 3 * 64) * (int)sizeof(float); // 85760
    cudaFuncSetAttribute(attn_kernel, cudaFuncAttributeMaxDynamicSharedMemorySize, attn_smem);

    dim3 blk(256);
    // projections
    sgemm128<<<dim3(QKW / 128, MROWS / 128), blk>>>(x, Wq, gq, nullptr, MROWS, QKW, DIMM);
    sgemm128<<<dim3(QKW / 128, MROWS / 128), blk>>>(x, Wk, gk, nullptr, MROWS, QKW, DIMM);
    sgemm128<<<dim3(VW  / 128, MROWS / 128), blk>>>(x, Wv, gv, nullptr, MROWS, VW,  DIMM);
    // attention
    attn_kernel<<<dim3(NSEQ / 64, HEADS, BATCH), blk, attn_smem>>>(gq, gk, gv, pos, rb, gao);
    // output projection + bias
    sgemm128<<<dim3(DIMM / 128, MROWS / 128), blk>>>(gao, Wo, out, bo, MROWS, DIMM, DIMM);
}

// round 12
// speedup vs baseline: 1.5257x; 1.5257x over previous
#include <cuda_runtime.h>
#include <cuda_bf16.h>
#include <cstdint>

typedef unsigned long long u64t;

#define BATCH 2
#define NSEQ  2048
#define DIMM  1536
#define HEADS 8
#define DK    64
#define DV    192
#define QSCALE 0.125f

#define MROWS (BATCH*NSEQ)          // 4096
#define QKW   (HEADS*DK)            // 512
#define VW    (HEADS*DV)            // 1536

// ---- static device scratch (allocation-free) ----
__device__ float g_q  [MROWS * QKW];
__device__ float g_k  [MROWS * QKW];
__device__ float g_v  [MROWS * VW];
__device__ float g_ao [MROWS * VW];
__device__ float g_wqT[QKW * DIMM];
__device__ float g_wkT[QKW * DIMM];
__device__ float g_wvT[VW  * DIMM];
__device__ float g_woT[DIMM * DIMM];

// =========================== common helpers ================================
__device__ __forceinline__ u64t pack2(float x, float y) {
    u64t r; asm("mov.b64 %0, {%1, %2};" : "=l"(r) : "f"(x), "f"(y)); return r;
}
__device__ __forceinline__ void fma2(u64t& d, u64t a, u64t b) {
    asm("fma.rn.f32x2 %0, %1, %2, %0;" : "+l"(d) : "l"(a), "l"(b));
}
__device__ __forceinline__ void mul2(u64t& d, u64t a, u64t b) {
    asm("mul.rn.f32x2 %0, %1, %2;" : "=l"(d) : "l"(a), "l"(b));
}
__device__ __forceinline__ uint32_t tf32r(float x) {
    uint32_t r; asm("cvt.rna.tf32.f32 %0, %1;" : "=r"(r) : "f"(x)); return r;
}

__device__ __forceinline__ void mma1688(float* d, const uint32_t* a, const uint32_t* b) {
    asm volatile(
        "mma.sync.aligned.m16n8k8.row.col.f32.tf32.tf32.f32 "
        "{%0,%1,%2,%3}, {%4,%5,%6,%7}, {%8,%9}, {%0,%1,%2,%3};"
        : "+f"(d[0]), "+f"(d[1]), "+f"(d[2]), "+f"(d[3])
        : "r"(a[0]), "r"(a[1]), "r"(a[2]), "r"(a[3]), "r"(b[0]), "r"(b[1]));
}

// ======================= transpose (B -> K-major) ==========================
__global__ void transpose_k(const float* __restrict__ src, float* __restrict__ dst,
                            int R, int C)
{
    __shared__ float t[32][33];
    const int c  = blockIdx.x * 32 + threadIdx.x;
    const int r0 = blockIdx.y * 32;
    #pragma unroll
    for (int j = threadIdx.y; j < 32; j += 8)
        t[j][threadIdx.x] = src[(size_t)(r0 + j) * C + c];
    __syncthreads();
    const int rr  = r0 + threadIdx.x;
    const int cc0 = blockIdx.x * 32;
    #pragma unroll
    for (int j = threadIdx.y; j < 32; j += 8)
        dst[(size_t)(cc0 + j) * R + rr] = t[threadIdx.x][j];
}

// ===================== tensor-core tf32 GEMM (mma.sync) ====================
// C[M,Ntot] = A[M,K] @ Bt[Ntot,K]^T (+bias). 128x128 tile, K-chunk 32,
// 256 threads = 8 warps (2 x 4), each warp 64x32 via m16n8k8 tf32.
// SPLIT=1: 2-term tf32 split (hi*hi + hi*lo + lo*hi) for precision.
#define GP 36   // smem pitch in floats (conflict-free for fragment loads)

template<int SPLIT>
__global__ __launch_bounds__(256)
void gemm_mma(const float* __restrict__ A, const float* __restrict__ Bt,
              float* __restrict__ C, const float* __restrict__ bias,
              int M, int Ntot, int K)
{
    extern __shared__ uint32_t smu[];
    uint32_t* As  = smu;                 // [128][GP]
    uint32_t* Bs  = As + 128 * GP;
    uint32_t* Asl = Bs + 128 * GP;       // lo parts (SPLIT only)
    uint32_t* Bsl = Asl + 128 * GP;

    const int tid  = threadIdx.x;
    const int lane = tid & 31;
    const int g    = lane >> 2;          // 0..7
    const int tg   = lane & 3;           // 0..3
    const int wid  = tid >> 5;
    const int wr   = (wid & 1) * 64;     // warp row offset within tile
    const int wc   = (wid >> 1) * 32;    // warp col offset within tile
    const int brow = blockIdx.y * 128;
    const int bcol = blockIdx.x * 128;

    const float* Ab = A  + (size_t)brow * K;
    const float* Bb = Bt + (size_t)bcol * K;
    const int nch = K >> 5;

    float d[4][4][4];
    #pragma unroll
    for (int mt = 0; mt < 4; mt++)
        #pragma unroll
        for (int nt = 0; nt < 4; nt++)
            #pragma unroll
            for (int i = 0; i < 4; i++) d[mt][nt][i] = 0.0f;

    // prefetch chunk 0 (each thread: 4 float4 of A, 4 of B)
    float4 pa[4], pb[4];
    #pragma unroll
    for (int l = 0; l < 4; l++) {
        int e = tid + l * 256;
        int row = e >> 3, c4 = (e & 7) << 2;
        pa[l] = *(const float4*)(Ab + (size_t)row * K + c4);
        pb[l] = *(const float4*)(Bb + (size_t)row * K + c4);
    }

    for (int c = 0; c < nch; ++c) {
        __syncthreads();   // previous chunk fully consumed
        #pragma unroll
        for (int l = 0; l < 4; l++) {
            int e = tid + l * 256;
            int row = e >> 3, c4 = (e & 7) << 2;
            uint32_t* ap = As + row * GP + c4;
            uint32_t* bp = Bs + row * GP + c4;
            uint4 ha = { tf32r(pa[l].x), tf32r(pa[l].y), tf32r(pa[l].z), tf32r(pa[l].w) };
            uint4 hb = { tf32r(pb[l].x), tf32r(pb[l].y), tf32r(pb[l].z), tf32r(pb[l].w) };
            *(uint4*)ap = ha;
            *(uint4*)bp = hb;
            if (SPLIT) {
                uint4 la = { tf32r(pa[l].x - __uint_as_float(ha.x)),
                             tf32r(pa[l].y - __uint_as_float(ha.y)),
                             tf32r(pa[l].z - __uint_as_float(ha.z)),
                             tf32r(pa[l].w - __uint_as_float(ha.w)) };
                uint4 lb = { tf32r(pb[l].x - __uint_as_float(hb.x)),
                             tf32r(pb[l].y - __uint_as_float(hb.y)),
                             tf32r(pb[l].z - __uint_as_float(hb.z)),
                             tf32r(pb[l].w - __uint_as_float(hb.w)) };
                *(uint4*)(Asl + row * GP + c4) = la;
                *(uint4*)(Bsl + row * GP + c4) = lb;
            }
        }
        __syncthreads();

        if (c + 1 < nch) {
            const int k0 = (c + 1) << 5;
            #pragma unroll
            for (int l = 0; l < 4; l++) {
                int e = tid + l * 256;
                int row = e >> 3, c4 = (e & 7) << 2;
                pa[l] = *(const float4*)(Ab + (size_t)row * K + k0 + c4);
                pb[l] = *(const float4*)(Bb + (size_t)row * K + k0 + c4);
            }
        }

        #pragma unroll
        for (int ks = 0; ks < 4; ks++) {
            const int k8 = ks * 8;
            uint32_t af[4][4], bf[4][2];
            #pragma unroll
            for (int mt = 0; mt < 4; mt++) {
                const uint32_t* ap = As + (wr + mt * 16 + g) * GP + k8 + tg;
                af[mt][0] = ap[0];
                af[mt][2] = ap[4];
                af[mt][1] = ap[8 * GP];
                af[mt][3] = ap[8 * GP + 4];
            }
            #pragma unroll
            for (int nt = 0; nt < 4; nt++) {
                const uint32_t* bp = Bs + (wc + nt * 8 + g) * GP + k8 + tg;
                bf[nt][0] = bp[0];
                bf[nt][1] = bp[4];
            }
            #pragma unroll
            for (int mt = 0; mt < 4; mt++)
                #pragma unroll
                for (int nt = 0; nt < 4; nt++)
                    mma1688(d[mt][nt], af[mt], bf[nt]);

            if (SPLIT) {
                // hi(A) * lo(B)
                uint32_t bl[4][2];
                #pragma unroll
                for (int nt = 0; nt < 4; nt++) {
                    const uint32_t* bp = Bsl + (wc + nt * 8 + g) * GP + k8 + tg;
                    bl[nt][0] = bp[0];
                    bl[nt][1] = bp[4];
                }
                #pragma unroll
                for (int mt = 0; mt < 4; mt++)
                    #pragma unroll
                    for (int nt = 0; nt < 4; nt++)
                        mma1688(d[mt][nt], af[mt], bl[nt]);
                // lo(A) * hi(B)
                uint32_t al[4][4];
                #pragma unroll
                for (int mt = 0; mt < 4; mt++) {
                    const uint32_t* ap = Asl + (wr + mt * 16 + g) * GP + k8 + tg;
                    al[mt][0] = ap[0];
                    al[mt][2] = ap[4];
                    al[mt][1] = ap[8 * GP];
                    al[mt][3] = ap[8 * GP + 4];
                }
                #pragma unroll
                for (int mt = 0; mt < 4; mt++)
                    #pragma unroll
                    for (int nt = 0; nt < 4; nt++)
                        mma1688(d[mt][nt], al[mt], bf[nt]);
            }
        }
    }

    // epilogue: c0:(g,2tg) c1:(g,2tg+1) c2:(g+8,2tg) c3:(g+8,2tg+1)
    #pragma unroll
    for (int mt = 0; mt < 4; mt++) {
        const int row0 = brow + wr + mt * 16 + g;
        #pragma unroll
        for (int nt = 0; nt < 4; nt++) {
            const int col = bcol + wc + nt * 8 + 2 * tg;
            float2 v0 = { d[mt][nt][0], d[mt][nt][1] };
            float2 v1 = { d[mt][nt][2], d[mt][nt][3] };
            if (bias) {
                float2 bv = *(const float2*)(bias + col);
                v0.x += bv.x; v0.y += bv.y;
                v1.x += bv.x; v1.y += bv.y;
            }
            *(float2*)(C + (size_t)row0 * Ntot + col)       = v0;
            *(float2*)(C + (size_t)(row0 + 8) * Ntot + col) = v1;
        }
    }
}

// ===================== flash attention (fp32, f32x2) =======================
#define QROW 68
#define VROW 196

__global__ __launch_bounds__(256, 2)
void attn_kernel(const float* __restrict__ qp, const float* __restrict__ kp,
                 const float* __restrict__ vp, const float* __restrict__ pos,
                 const float* __restrict__ relb, float* __restrict__ out)
{
    extern __shared__ float smf[];
    float* Qs   = smf;                 // 64 x QROW
    float* Ps   = Qs + 64 * QROW;      // K tile, then reused as P tile
    float* Vs   = Ps + 64 * QROW;      // 64 x VROW
    float* mrow = Vs + 64 * VROW;      // 64
    float* lrow = mrow + 64;           // 64
    float* srow = lrow + 64;           // 64

    const int tid = threadIdx.x;
    const int tx  = tid & 15, ty = tid >> 4;
    const int r0  = ty * 4;
    const int c0  = tx * 12;
    const int b   = blockIdx.z, h = blockIdx.y;
    const int q0  = blockIdx.x * 64;

    const float* qb = qp + (size_t)b * NSEQ * QKW + h * DK;
    const float* kb = kp + (size_t)b * NSEQ * QKW + h * DK;
    const float* vb = vp + (size_t)b * NSEQ * VW  + h * DV;
    const float* pb = pos + (size_t)h * NSEQ * DK;

    #pragma unroll
    for (int l = 0; l < 4; l++) {
        int e = tid + l * 256;
        int r = e >> 4, d = (e & 15) << 2;
        float4 qv = *(const float4*)(qb + (size_t)(q0 + r) * QKW + d);
        float4 pv = *(const float4*)(pb + (size_t)(q0 + r) * DK + d);
        float4 rv = *(const float4*)(relb + h * DK + d);
        float4 o4;
        o4.x = qv.x * QSCALE + pv.x + rv.x;
        o4.y = qv.y * QSCALE + pv.y + rv.y;
        o4.z = qv.z * QSCALE + pv.z + rv.z;
        o4.w = qv.w * QSCALE + pv.w + rv.w;
        *(float4*)(Qs + r * QROW + d) = o4;
    }
    if (tid < 64) { mrow[tid] = -1e30f; lrow[tid] = 0.0f; }

    u64t oacc[4][6];
    #pragma unroll
    for (int i = 0; i < 4; i++)
        #pragma unroll
        for (int c = 0; c < 6; c++) oacc[i][c] = 0ull;

    for (int j0 = 0; j0 < NSEQ; j0 += 64) {
        __syncthreads();
        #pragma unroll
        for (int l = 0; l < 4; l++) {
            int e = tid + l * 256;
            int r = e >> 4, d = (e & 15) << 2;
            *(float4*)(Ps + r * QROW + d) =
                *(const float4*)(kb + (size_t)(j0 + r) * QKW + d);
        }
        #pragma unroll
        for (int l = 0; l < 12; l++) {
            int e = tid + l * 256;
            int r = e / 48, c = (e % 48) << 2;
            *(float4*)(Vs + r * VROW + c) =
                *(const float4*)(vb + (size_t)(j0 + r) * VW + c);
        }
        __syncthreads();

        // S = Q K^T with packed f32x2 accumulation over d
        u64t s2[4][4];
        #pragma unroll
        for (int i = 0; i < 4; i++)
            #pragma unroll
            for (int j = 0; j < 4; j++) s2[i][j] = 0ull;
        #pragma unroll
        for (int d = 0; d < DK; d += 4) {
            u64t qlo[4], qhi[4], klo[4], khi[4];
            #pragma unroll
            for (int i = 0; i < 4; i++) {
                const u64t* q2 = (const u64t*)(Qs + (r0 + i) * QROW + d);
                qlo[i] = q2[0]; qhi[i] = q2[1];
            }
            #pragma unroll
            for (int j = 0; j < 4; j++) {
                const u64t* k2 = (const u64t*)(Ps + (tx + 16 * j) * QROW + d);
                klo[j] = k2[0]; khi[j] = k2[1];
            }
            #pragma unroll
            for (int i = 0; i < 4; i++)
                #pragma unroll
                for (int j = 0; j < 4; j++) {
                    fma2(s2[i][j], qlo[i], klo[j]);
                    fma2(s2[i][j], qhi[i], khi[j]);
                }
        }
        float s[4][4];
        #pragma unroll
        for (int i = 0; i < 4; i++)
            #pragma unroll
            for (int j = 0; j < 4; j++) {
                float2 f = *(float2*)&s2[i][j];
                s[i][j] = f.x + f.y;
            }

        float rm[4];
        #pragma unroll
        for (int i = 0; i < 4; i++) {
            rm[i] = fmaxf(fmaxf(s[i][0], s[i][1]), fmaxf(s[i][2], s[i][3]));
            #pragma unroll
            for (int o = 8; o > 0; o >>= 1)
                rm[i] = fmaxf(rm[i], __shfl_xor_sync(0xffffffffu, rm[i], o));
        }
        if (tx == 0) {
            #pragma unroll
            for (int i = 0; i < 4; i++) {
                float mo = mrow[r0 + i];
                float mn = fmaxf(mo, rm[i]);
                srow[r0 + i] = __expf(mo - mn);
                mrow[r0 + i] = mn;
            }
        }
        __syncthreads();

        float rs[4];
        #pragma unroll
        for (int i = 0; i < 4; i++) {
            float mi = mrow[r0 + i];
            float p0 = __expf(s[i][0] - mi);
            float p1 = __expf(s[i][1] - mi);
            float p2 = __expf(s[i][2] - mi);
            float p3 = __expf(s[i][3] - mi);
            float* pr = Ps + (r0 + i) * QROW;
            pr[tx] = p0; pr[tx + 16] = p1; pr[tx + 32] = p2; pr[tx + 48] = p3;
            rs[i] = (p0 + p1) + (p2 + p3);
            #pragma unroll
            for (int o = 8; o > 0; o >>= 1)
                rs[i] += __shfl_xor_sync(0xffffffffu, rs[i], o);
        }
        if (tx == 0) {
            #pragma unroll
            for (int i = 0; i < 4; i++)
                lrow[r0 + i] = lrow[r0 + i] * srow[r0 + i] + rs[i];
        }
        __syncthreads();

        #pragma unroll
        for (int i = 0; i < 4; i++) {
            float sc = srow[r0 + i];
            u64t sd = pack2(sc, sc);
            #pragma unroll
            for (int c = 0; c < 6; c++) mul2(oacc[i][c], oacc[i][c], sd);
        }
        #pragma unroll 4
        for (int j4 = 0; j4 < 64; j4 += 4) {
            float4 p4[4];
            #pragma unroll
            for (int i = 0; i < 4; i++)
                p4[i] = *(const float4*)(Ps + (r0 + i) * QROW + j4);
            #pragma unroll
            for (int sj = 0; sj < 4; sj++) {
                const u64t* vr = (const u64t*)(Vs + (size_t)(j4 + sj) * VROW + c0);
                u64t v0 = vr[0], v1 = vr[1], v2 = vr[2], v3 = vr[3], v4 = vr[4], v5 = vr[5];
                #pragma unroll
                for (int i = 0; i < 4; i++) {
                    float pv = (sj == 0) ? p4[i].x : (sj == 1) ? p4[i].y
                             : (sj == 2) ? p4[i].z : p4[i].w;
                    u64t pd = pack2(pv, pv);
                    fma2(oacc[i][0], pd, v0);
                    fma2(oacc[i][1], pd, v1);
                    fma2(oacc[i][2], pd, v2);
                    fma2(oacc[i][3], pd, v3);
                    fma2(oacc[i][4], pd, v4);
                    fma2(oacc[i][5], pd, v5);
                }
            }
        }
    }

    #pragma unroll
    for (int i = 0; i < 4; i++) {
        float inv = 1.0f / lrow[r0 + i];
        float res[12];
        #pragma unroll
        for (int c = 0; c < 6; c++) {
            float2 f = *(float2*)&oacc[i][c];
            res[2 * c]     = f.x * inv;
            res[2 * c + 1] = f.y * inv;
        }
        float* ob = out + (size_t)(b * NSEQ + q0 + r0 + i) * VW + h * DV + c0;
        *(float4*)(ob)     = *(float4*)(res);
        *(float4*)(ob + 4) = *(float4*)(res + 4);
        *(float4*)(ob + 8) = *(float4*)(res + 8);
    }
}

// ---------------------------------------------------------------------------
extern "C" void kernel_launch(void* const* d_in, const int* in_sizes, int n_in,
                              void* d_out, int out_size)
{
    (void)in_sizes; (void)n_in; (void)out_size;
    const float* x   = (const float*)d_in[0];
    const float* Wq  = (const float*)d_in[1];
    const float* Wk  = (const float*)d_in[2];
    const float* Wv  = (const float*)d_in[3];
    const float* Wo  = (const float*)d_in[4];
    const float* bo  = (const float*)d_in[5];
    const float* pos = (const float*)d_in[6];
    const float* rb  = (const float*)d_in[7];
    float* out = (float*)d_out;

    float *gq, *gk, *gv, *gao, *wqT, *wkT, *wvT, *woT;
    cudaGetSymbolAddress((void**)&gq,  g_q);
    cudaGetSymbolAddress((void**)&gk,  g_k);
    cudaGetSymbolAddress((void**)&gv,  g_v);
    cudaGetSymbolAddress((void**)&gao, g_ao);
    cudaGetSymbolAddress((void**)&wqT, g_wqT);
    cudaGetSymbolAddress((void**)&wkT, g_wkT);
    cudaGetSymbolAddress((void**)&wvT, g_wvT);
    cudaGetSymbolAddress((void**)&woT, g_woT);

    const int attn_smem = (64 * QROW * 2 + 64 * VROW + 3 * 64) * (int)sizeof(float);
    const int gsmem0 = 2 * 128 * GP * 4;   // As + Bs
    const int gsmem1 = 4 * 128 * GP * 4;   // + lo buffers
    cudaFuncSetAttribute(attn_kernel, cudaFuncAttributeMaxDynamicSharedMemorySize, attn_smem);
    cudaFuncSetAttribute(gemm_mma<0>, cudaFuncAttributeMaxDynamicSharedMemorySize, gsmem0);
    cudaFuncSetAttribute(gemm_mma<1>, cudaFuncAttributeMaxDynamicSharedMemorySize, gsmem1);

    dim3 tb(32, 8);
    // weight transposes (raw f32; GEMM loader does tf32 rounding)
    transpose_k<<<dim3(QKW / 32,  DIMM / 32), tb>>>(Wq, wqT, DIMM, QKW);
    transpose_k<<<dim3(QKW / 32,  DIMM / 32), tb>>>(Wk, wkT, DIMM, QKW);
    transpose_k<<<dim3(VW  / 32,  DIMM / 32), tb>>>(Wv, wvT, DIMM, VW);
    transpose_k<<<dim3(DIMM / 32, VW  / 32),  tb>>>(Wo, woT, VW,  DIMM);

    // projections (tensor cores; K uses split-tf32 for precision)
    gemm_mma<0><<<dim3(QKW / 128, MROWS / 128), 256, gsmem0>>>(x, wqT, gq, nullptr, MROWS, QKW, DIMM);
    gemm_mma<1><<<dim3(QKW / 128, MROWS / 128), 256, gsmem1>>>(x, wkT, gk, nullptr, MROWS, QKW, DIMM);
    gemm_mma<0><<<dim3(VW  / 128, MROWS / 128), 256, gsmem0>>>(x, wvT, gv, nullptr, MROWS, VW,  DIMM);

    attn_kernel<<<dim3(NSEQ / 64, HEADS, BATCH), 256, attn_smem>>>(gq, gk, gv, pos, rb, gao);

    // output projection + bias
    gemm_mma<0><<<dim3(DIMM / 128, MROWS / 128), 256, gsmem0>>>(gao, woT, out, bo, MROWS, DIMM, VW);
}

// round 13
// speedup vs baseline: 1.5257x; 1.0000x over previous
#include <cuda_runtime.h>
#include <cuda_bf16.h>
#include <cstdint>

typedef unsigned long long u64t;

#define BATCH 2
#define NSEQ  2048
#define DIMM  1536
#define HEADS 8
#define DK    64
#define DV    192
#define QSCALE 0.125f

#define MROWS (BATCH*NSEQ)          // 4096
#define QKW   (HEADS*DK)            // 512
#define VW    (HEADS*DV)            // 1536

// ---- static device scratch (allocation-free) ----
__device__ float g_q  [MROWS * QKW];
__device__ float g_k  [MROWS * QKW];
__device__ float g_v  [MROWS * VW];
__device__ float g_ao [MROWS * VW];
__device__ float g_wqT[QKW * DIMM];
__device__ float g_wkT[QKW * DIMM];
__device__ float g_wvT[VW  * DIMM];
__device__ float g_woT[DIMM * DIMM];

// =========================== common helpers ================================
__device__ __forceinline__ u64t pack2(float x, float y) {
    u64t r; asm("mov.b64 %0, {%1, %2};" : "=l"(r) : "f"(x), "f"(y)); return r;
}
__device__ __forceinline__ void fma2(u64t& d, u64t a, u64t b) {
    asm("fma.rn.f32x2 %0, %1, %2, %0;" : "+l"(d) : "l"(a), "l"(b));
}
__device__ __forceinline__ void mul2(u64t& d, u64t a, u64t b) {
    asm("mul.rn.f32x2 %0, %1, %2;" : "=l"(d) : "l"(a), "l"(b));
}
__device__ __forceinline__ uint32_t tf32r(float x) {
    uint32_t r; asm("cvt.rna.tf32.f32 %0, %1;" : "=r"(r) : "f"(x)); return r;
}

__device__ __forceinline__ void mma1688(float* d, const uint32_t* a, const uint32_t* b) {
    asm volatile(
        "mma.sync.aligned.m16n8k8.row.col.f32.tf32.tf32.f32 "
        "{%0,%1,%2,%3}, {%4,%5,%6,%7}, {%8,%9}, {%0,%1,%2,%3};"
        : "+f"(d[0]), "+f"(d[1]), "+f"(d[2]), "+f"(d[3])
        : "r"(a[0]), "r"(a[1]), "r"(a[2]), "r"(a[3]), "r"(b[0]), "r"(b[1]));
}

// ======================= transpose (B -> K-major) ==========================
__global__ void transpose_k(const float* __restrict__ src, float* __restrict__ dst,
                            int R, int C)
{
    __shared__ float t[32][33];
    const int c  = blockIdx.x * 32 + threadIdx.x;
    const int r0 = blockIdx.y * 32;
    #pragma unroll
    for (int j = threadIdx.y; j < 32; j += 8)
        t[j][threadIdx.x] = src[(size_t)(r0 + j) * C + c];
    __syncthreads();
    const int rr  = r0 + threadIdx.x;
    const int cc0 = blockIdx.x * 32;
    #pragma unroll
    for (int j = threadIdx.y; j < 32; j += 8)
        dst[(size_t)(cc0 + j) * R + rr] = t[threadIdx.x][j];
}

// ===================== tensor-core tf32 GEMM (mma.sync) ====================
// C[M,Ntot] = A[M,K] @ Bt[Ntot,K]^T (+bias). 128x128 tile, K-chunk 32,
// 256 threads = 8 warps (2 x 4), each warp 64x32 via m16n8k8 tf32.
// SPLIT=1: 2-term tf32 split (hi*hi + hi*lo + lo*hi) for precision.
#define GP 36   // smem pitch in floats (conflict-free for fragment loads)

template<int SPLIT>
__global__ __launch_bounds__(256)
void gemm_mma(const float* __restrict__ A, const float* __restrict__ Bt,
              float* __restrict__ C, const float* __restrict__ bias,
              int M, int Ntot, int K)
{
    extern __shared__ uint32_t smu[];
    uint32_t* As  = smu;                 // [128][GP]
    uint32_t* Bs  = As + 128 * GP;
    uint32_t* Asl = Bs + 128 * GP;       // lo parts (SPLIT only)
    uint32_t* Bsl = Asl + 128 * GP;

    const int tid  = threadIdx.x;
    const int lane = tid & 31;
    const int g    = lane >> 2;          // 0..7
    const int tg   = lane & 3;           // 0..3
    const int wid  = tid >> 5;
    const int wr   = (wid & 1) * 64;     // warp row offset within tile
    const int wc   = (wid >> 1) * 32;    // warp col offset within tile
    const int brow = blockIdx.y * 128;
    const int bcol = blockIdx.x * 128;

    const float* Ab = A  + (size_t)brow * K;
    const float* Bb = Bt + (size_t)bcol * K;
    const int nch = K >> 5;

    float d[4][4][4];
    #pragma unroll
    for (int mt = 0; mt < 4; mt++)
        #pragma unroll
        for (int nt = 0; nt < 4; nt++)
            #pragma unroll
            for (int i = 0; i < 4; i++) d[mt][nt][i] = 0.0f;

    // prefetch chunk 0 (each thread: 4 float4 of A, 4 of B)
    float4 pa[4], pb[4];
    #pragma unroll
    for (int l = 0; l < 4; l++) {
        int e = tid + l * 256;
        int row = e >> 3, c4 = (e & 7) << 2;
        pa[l] = *(const float4*)(Ab + (size_t)row * K + c4);
        pb[l] = *(const float4*)(Bb + (size_t)row * K + c4);
    }

    for (int c = 0; c < nch; ++c) {
        __syncthreads();   // previous chunk fully consumed
        #pragma unroll
        for (int l = 0; l < 4; l++) {
            int e = tid + l * 256;
            int row = e >> 3, c4 = (e & 7) << 2;
            uint32_t* ap = As + row * GP + c4;
            uint32_t* bp = Bs + row * GP + c4;
            uint4 ha = { tf32r(pa[l].x), tf32r(pa[l].y), tf32r(pa[l].z), tf32r(pa[l].w) };
            uint4 hb = { tf32r(pb[l].x), tf32r(pb[l].y), tf32r(pb[l].z), tf32r(pb[l].w) };
            *(uint4*)ap = ha;
            *(uint4*)bp = hb;
            if (SPLIT) {
                uint4 la = { tf32r(pa[l].x - __uint_as_float(ha.x)),
                             tf32r(pa[l].y - __uint_as_float(ha.y)),
                             tf32r(pa[l].z - __uint_as_float(ha.z)),
                             tf32r(pa[l].w - __uint_as_float(ha.w)) };
                uint4 lb = { tf32r(pb[l].x - __uint_as_float(hb.x)),
                             tf32r(pb[l].y - __uint_as_float(hb.y)),
                             tf32r(pb[l].z - __uint_as_float(hb.z)),
                             tf32r(pb[l].w - __uint_as_float(hb.w)) };
                *(uint4*)(Asl + row * GP + c4) = la;
                *(uint4*)(Bsl + row * GP + c4) = lb;
            }
        }
        __syncthreads();

        if (c + 1 < nch) {
            const int k0 = (c + 1) << 5;
            #pragma unroll
            for (int l = 0; l < 4; l++) {
                int e = tid + l * 256;
                int row = e >> 3, c4 = (e & 7) << 2;
                pa[l] = *(const float4*)(Ab + (size_t)row * K + k0 + c4);
                pb[l] = *(const float4*)(Bb + (size_t)row * K + k0 + c4);
            }
        }

        #pragma unroll
        for (int ks = 0; ks < 4; ks++) {
            const int k8 = ks * 8;
            uint32_t af[4][4], bf[4][2];
            #pragma unroll
            for (int mt = 0; mt < 4; mt++) {
                const uint32_t* ap = As + (wr + mt * 16 + g) * GP + k8 + tg;
                af[mt][0] = ap[0];
                af[mt][2] = ap[4];
                af[mt][1] = ap[8 * GP];
                af[mt][3] = ap[8 * GP + 4];
            }
            #pragma unroll
            for (int nt = 0; nt < 4; nt++) {
                const uint32_t* bp = Bs + (wc + nt * 8 + g) * GP + k8 + tg;
                bf[nt][0] = bp[0];
                bf[nt][1] = bp[4];
            }
            #pragma unroll
            for (int mt = 0; mt < 4; mt++)
                #pragma unroll
                for (int nt = 0; nt < 4; nt++)
                    mma1688(d[mt][nt], af[mt], bf[nt]);

            if (SPLIT) {
                // hi(A) * lo(B)
                uint32_t bl[4][2];
                #pragma unroll
                for (int nt = 0; nt < 4; nt++) {
                    const uint32_t* bp = Bsl + (wc + nt * 8 + g) * GP + k8 + tg;
                    bl[nt][0] = bp[0];
                    bl[nt][1] = bp[4];
                }
                #pragma unroll
                for (int mt = 0; mt < 4; mt++)
                    #pragma unroll
                    for (int nt = 0; nt < 4; nt++)
                        mma1688(d[mt][nt], af[mt], bl[nt]);
                // lo(A) * hi(B)
                uint32_t al[4][4];
                #pragma unroll
                for (int mt = 0; mt < 4; mt++) {
                    const uint32_t* ap = Asl + (wr + mt * 16 + g) * GP + k8 + tg;
                    al[mt][0] = ap[0];
                    al[mt][2] = ap[4];
                    al[mt][1] = ap[8 * GP];
                    al[mt][3] = ap[8 * GP + 4];
                }
                #pragma unroll
                for (int mt = 0; mt < 4; mt++)
                    #pragma unroll
                    for (int nt = 0; nt < 4; nt++)
                        mma1688(d[mt][nt], al[mt], bf[nt]);
            }
        }
    }

    // epilogue: c0:(g,2tg) c1:(g,2tg+1) c2:(g+8,2tg) c3:(g+8,2tg+1)
    #pragma unroll
    for (int mt = 0; mt < 4; mt++) {
        const int row0 = brow + wr + mt * 16 + g;
        #pragma unroll
        for (int nt = 0; nt < 4; nt++) {
            const int col = bcol + wc + nt * 8 + 2 * tg;
            float2 v0 = { d[mt][nt][0], d[mt][nt][1] };
            float2 v1 = { d[mt][nt][2], d[mt][nt][3] };
            if (bias) {
                float2 bv = *(const float2*)(bias + col);
                v0.x += bv.x; v0.y += bv.y;
                v1.x += bv.x; v1.y += bv.y;
            }
            *(float2*)(C + (size_t)row0 * Ntot + col)       = v0;
            *(float2*)(C + (size_t)(row0 + 8) * Ntot + col) = v1;
        }
    }
}

// ===================== flash attention (fp32, f32x2) =======================
#define QROW 68
#define VROW 196

__global__ __launch_bounds__(256, 2)
void attn_kernel(const float* __restrict__ qp, const float* __restrict__ kp,
                 const float* __restrict__ vp, const float* __restrict__ pos,
                 const float* __restrict__ relb, float* __restrict__ out)
{
    extern __shared__ float smf[];
    float* Qs   = smf;                 // 64 x QROW
    float* Ps   = Qs + 64 * QROW;      // K tile, then reused as P tile
    float* Vs   = Ps + 64 * QROW;      // 64 x VROW
    float* mrow = Vs + 64 * VROW;      // 64
    float* lrow = mrow + 64;           // 64
    float* srow = lrow + 64;           // 64

    const int tid = threadIdx.x;
    const int tx  = tid & 15, ty = tid >> 4;
    const int r0  = ty * 4;
    const int c0  = tx * 12;
    const int b   = blockIdx.z, h = blockIdx.y;
    const int q0  = blockIdx.x * 64;

    const float* qb = qp + (size_t)b * NSEQ * QKW + h * DK;
    const float* kb = kp + (size_t)b * NSEQ * QKW + h * DK;
    const float* vb = vp + (size_t)b * NSEQ * VW  + h * DV;
    const float* pb = pos + (size_t)h * NSEQ * DK;

    #pragma unroll
    for (int l = 0; l < 4; l++) {
        int e = tid + l * 256;
        int r = e >> 4, d = (e & 15) << 2;
        float4 qv = *(const float4*)(qb + (size_t)(q0 + r) * QKW + d);
        float4 pv = *(const float4*)(pb + (size_t)(q0 + r) * DK + d);
        float4 rv = *(const float4*)(relb + h * DK + d);
        float4 o4;
        o4.x = qv.x * QSCALE + pv.x + rv.x;
        o4.y = qv.y * QSCALE + pv.y + rv.y;
        o4.z = qv.z * QSCALE + pv.z + rv.z;
        o4.w = qv.w * QSCALE + pv.w + rv.w;
        *(float4*)(Qs + r * QROW + d) = o4;
    }
    if (tid < 64) { mrow[tid] = -1e30f; lrow[tid] = 0.0f; }

    u64t oacc[4][6];
    #pragma unroll
    for (int i = 0; i < 4; i++)
        #pragma unroll
        for (int c = 0; c < 6; c++) oacc[i][c] = 0ull;

    for (int j0 = 0; j0 < NSEQ; j0 += 64) {
        __syncthreads();
        #pragma unroll
        for (int l = 0; l < 4; l++) {
            int e = tid + l * 256;
            int r = e >> 4, d = (e & 15) << 2;
            *(float4*)(Ps + r * QROW + d) =
                *(const float4*)(kb + (size_t)(j0 + r) * QKW + d);
        }
        #pragma unroll
        for (int l = 0; l < 12; l++) {
            int e = tid + l * 256;
            int r = e / 48, c = (e % 48) << 2;
            *(float4*)(Vs + r * VROW + c) =
                *(const float4*)(vb + (size_t)(j0 + r) * VW + c);
        }
        __syncthreads();

        // S = Q K^T with packed f32x2 accumulation over d
        u64t s2[4][4];
        #pragma unroll
        for (int i = 0; i < 4; i++)
            #pragma unroll
            for (int j = 0; j < 4; j++) s2[i][j] = 0ull;
        #pragma unroll
        for (int d = 0; d < DK; d += 4) {
            u64t qlo[4], qhi[4], klo[4], khi[4];
            #pragma unroll
            for (int i = 0; i < 4; i++) {
                const u64t* q2 = (const u64t*)(Qs + (r0 + i) * QROW + d);
                qlo[i] = q2[0]; qhi[i] = q2[1];
            }
            #pragma unroll
            for (int j = 0; j < 4; j++) {
                const u64t* k2 = (const u64t*)(Ps + (tx + 16 * j) * QROW + d);
                klo[j] = k2[0]; khi[j] = k2[1];
            }
            #pragma unroll
            for (int i = 0; i < 4; i++)
                #pragma unroll
                for (int j = 0; j < 4; j++) {
                    fma2(s2[i][j], qlo[i], klo[j]);
                    fma2(s2[i][j], qhi[i], khi[j]);
                }
        }
        float s[4][4];
        #pragma unroll
        for (int i = 0; i < 4; i++)
            #pragma unroll
            for (int j = 0; j < 4; j++) {
                float2 f = *(float2*)&s2[i][j];
                s[i][j] = f.x + f.y;
            }

        float rm[4];
        #pragma unroll
        for (int i = 0; i < 4; i++) {
            rm[i] = fmaxf(fmaxf(s[i][0], s[i][1]), fmaxf(s[i][2], s[i][3]));
            #pragma unroll
            for (int o = 8; o > 0; o >>= 1)
                rm[i] = fmaxf(rm[i], __shfl_xor_sync(0xffffffffu, rm[i], o));
        }
        if (tx == 0) {
            #pragma unroll
            for (int i = 0; i < 4; i++) {
                float mo = mrow[r0 + i];
                float mn = fmaxf(mo, rm[i]);
                srow[r0 + i] = __expf(mo - mn);
                mrow[r0 + i] = mn;
            }
        }
        __syncthreads();

        float rs[4];
        #pragma unroll
        for (int i = 0; i < 4; i++) {
            float mi = mrow[r0 + i];
            float p0 = __expf(s[i][0] - mi);
            float p1 = __expf(s[i][1] - mi);
            float p2 = __expf(s[i][2] - mi);
            float p3 = __expf(s[i][3] - mi);
            float* pr = Ps + (r0 + i) * QROW;
            pr[tx] = p0; pr[tx + 16] = p1; pr[tx + 32] = p2; pr[tx + 48] = p3;
            rs[i] = (p0 + p1) + (p2 + p3);
            #pragma unroll
            for (int o = 8; o > 0; o >>= 1)
                rs[i] += __shfl_xor_sync(0xffffffffu, rs[i], o);
        }
        if (tx == 0) {
            #pragma unroll
            for (int i = 0; i < 4; i++)
                lrow[r0 + i] = lrow[r0 + i] * srow[r0 + i] + rs[i];
        }
        __syncthreads();

        #pragma unroll
        for (int i = 0; i < 4; i++) {
            float sc = srow[r0 + i];
            u64t sd = pack2(sc, sc);
            #pragma unroll
            for (int c = 0; c < 6; c++) mul2(oacc[i][c], oacc[i][c], sd);
        }
        #pragma unroll 4
        for (int j4 = 0; j4 < 64; j4 += 4) {
            float4 p4[4];
            #pragma unroll
            for (int i = 0; i < 4; i++)
                p4[i] = *(const float4*)(Ps + (r0 + i) * QROW + j4);
            #pragma unroll
            for (int sj = 0; sj < 4; sj++) {
                const u64t* vr = (const u64t*)(Vs + (size_t)(j4 + sj) * VROW + c0);
                u64t v0 = vr[0], v1 = vr[1], v2 = vr[2], v3 = vr[3], v4 = vr[4], v5 = vr[5];
                #pragma unroll
                for (int i = 0; i < 4; i++) {
                    float pv = (sj == 0) ? p4[i].x : (sj == 1) ? p4[i].y
                             : (sj == 2) ? p4[i].z : p4[i].w;
                    u64t pd = pack2(pv, pv);
                    fma2(oacc[i][0], pd, v0);
                    fma2(oacc[i][1], pd, v1);
                    fma2(oacc[i][2], pd, v2);
                    fma2(oacc[i][3], pd, v3);
                    fma2(oacc[i][4], pd, v4);
                    fma2(oacc[i][5], pd, v5);
                }
            }
        }
    }

    #pragma unroll
    for (int i = 0; i < 4; i++) {
        float inv = 1.0f / lrow[r0 + i];
        float res[12];
        #pragma unroll
        for (int c = 0; c < 6; c++) {
            float2 f = *(float2*)&oacc[i][c];
            res[2 * c]     = f.x * inv;
            res[2 * c + 1] = f.y * inv;
        }
        float* ob = out + (size_t)(b * NSEQ + q0 + r0 + i) * VW + h * DV + c0;
        *(float4*)(ob)     = *(float4*)(res);
        *(float4*)(ob + 4) = *(float4*)(res + 4);
        *(float4*)(ob + 8) = *(float4*)(res + 8);
    }
}

// ---------------------------------------------------------------------------
extern "C" void kernel_launch(void* const* d_in, const int* in_sizes, int n_in,
                              void* d_out, int out_size)
{
    (void)in_sizes; (void)n_in; (void)out_size;
    const float* x   = (const float*)d_in[0];
    const float* Wq  = (const float*)d_in[1];
    const float* Wk  = (const float*)d_in[2];
    const float* Wv  = (const float*)d_in[3];
    const float* Wo  = (const float*)d_in[4];
    const float* bo  = (const float*)d_in[5];
    const float* pos = (const float*)d_in[6];
    const float* rb  = (const float*)d_in[7];
    float* out = (float*)d_out;

    float *gq, *gk, *gv, *gao, *wqT, *wkT, *wvT, *woT;
    cudaGetSymbolAddress((void**)&gq,  g_q);
    cudaGetSymbolAddress((void**)&gk,  g_k);
    cudaGetSymbolAddress((void**)&gv,  g_v);
    cudaGetSymbolAddress((void**)&gao, g_ao);
    cudaGetSymbolAddress((void**)&wqT, g_wqT);
    cudaGetSymbolAddress((void**)&wkT, g_wkT);
    cudaGetSymbolAddress((void**)&wvT, g_wvT);
    cudaGetSymbolAddress((void**)&woT, g_woT);

    const int attn_smem = (64 * QROW * 2 + 64 * VROW + 3 * 64) * (int)sizeof(float);
    const int gsmem0 = 2 * 128 * GP * 4;   // As + Bs
    const int gsmem1 = 4 * 128 * GP * 4;   // + lo buffers
    cudaFuncSetAttribute(attn_kernel, cudaFuncAttributeMaxDynamicSharedMemorySize, attn_smem);
    cudaFuncSetAttribute(gemm_mma<0>, cudaFuncAttributeMaxDynamicSharedMemorySize, gsmem0);
    cudaFuncSetAttribute(gemm_mma<1>, cudaFuncAttributeMaxDynamicSharedMemorySize, gsmem1);

    dim3 tb(32, 8);
    // weight transposes (raw f32; GEMM loader does tf32 rounding)
    transpose_k<<<dim3(QKW / 32,  DIMM / 32), tb>>>(Wq, wqT, DIMM, QKW);
    transpose_k<<<dim3(QKW / 32,  DIMM / 32), tb>>>(Wk, wkT, DIMM, QKW);
    transpose_k<<<dim3(VW  / 32,  DIMM / 32), tb>>>(Wv, wvT, DIMM, VW);
    transpose_k<<<dim3(DIMM / 32, VW  / 32),  tb>>>(Wo, woT, VW,  DIMM);

    // projections (tensor cores; K uses split-tf32 for precision)
    gemm_mma<0><<<dim3(QKW / 128, MROWS / 128), 256, gsmem0>>>(x, wqT, gq, nullptr, MROWS, QKW, DIMM);
    gemm_mma<1><<<dim3(QKW / 128, MROWS / 128), 256, gsmem1>>>(x, wkT, gk, nullptr, MROWS, QKW, DIMM);
    gemm_mma<0><<<dim3(VW  / 128, MROWS / 128), 256, gsmem0>>>(x, wvT, gv, nullptr, MROWS, VW,  DIMM);

    attn_kernel<<<dim3(NSEQ / 64, HEADS, BATCH), 256, attn_smem>>>(gq, gk, gv, pos, rb, gao);

    // output projection + bias
    gemm_mma<0><<<dim3(DIMM / 128, MROWS / 128), 256, gsmem0>>>(gao, woT, out, bo, MROWS, DIMM, VW);
}

// round 14
// speedup vs baseline: 2.2125x; 1.4502x over previous
#include <cuda_runtime.h>
#include <cuda_bf16.h>
#include <cstdint>

typedef unsigned long long u64t;

#define BATCH 2
#define NSEQ  2048
#define DIMM  1536
#define HEADS 8
#define DK    64
#define DV    192
#define QSCALE 0.125f

#define MROWS (BATCH*NSEQ)          // 4096
#define QKW   (HEADS*DK)            // 512
#define VW    (HEADS*DV)            // 1536

// ---- static device scratch (allocation-free) ----
__device__ float g_q  [MROWS * QKW];
__device__ float g_k  [MROWS * QKW];
__device__ float g_v  [MROWS * VW];
__device__ float g_ao [MROWS * VW];
__device__ float g_wqT[QKW * DIMM];
__device__ float g_wkT[QKW * DIMM];
__device__ float g_wvT[VW  * DIMM];
__device__ float g_woT[DIMM * DIMM];

// =========================== common helpers ================================
__device__ __forceinline__ uint32_t tf32r(float x) {
    uint32_t r; asm("cvt.rna.tf32.f32 %0, %1;" : "=r"(r) : "f"(x)); return r;
}

__device__ __forceinline__ void mma1688(float* d, const uint32_t* a, const uint32_t* b) {
    asm volatile(
        "mma.sync.aligned.m16n8k8.row.col.f32.tf32.tf32.f32 "
        "{%0,%1,%2,%3}, {%4,%5,%6,%7}, {%8,%9}, {%0,%1,%2,%3};"
        : "+f"(d[0]), "+f"(d[1]), "+f"(d[2]), "+f"(d[3])
        : "r"(a[0]), "r"(a[1]), "r"(a[2]), "r"(a[3]), "r"(b[0]), "r"(b[1]));
}

// ======================= transpose (B -> K-major) ==========================
__global__ void transpose_k(const float* __restrict__ src, float* __restrict__ dst,
                            int R, int C)
{
    __shared__ float t[32][33];
    const int c  = blockIdx.x * 32 + threadIdx.x;
    const int r0 = blockIdx.y * 32;
    #pragma unroll
    for (int j = threadIdx.y; j < 32; j += 8)
        t[j][threadIdx.x] = src[(size_t)(r0 + j) * C + c];
    __syncthreads();
    const int rr  = r0 + threadIdx.x;
    const int cc0 = blockIdx.x * 32;
    #pragma unroll
    for (int j = threadIdx.y; j < 32; j += 8)
        dst[(size_t)(cc0 + j) * R + rr] = t[threadIdx.x][j];
}

// ===================== tensor-core tf32 GEMM (mma.sync) ====================
#define GP 36   // smem pitch in floats

template<int SPLIT>
__global__ __launch_bounds__(256)
void gemm_mma(const float* __restrict__ A, const float* __restrict__ Bt,
              float* __restrict__ C, const float* __restrict__ bias,
              int M, int Ntot, int K)
{
    extern __shared__ uint32_t smu[];
    uint32_t* As  = smu;                 // [128][GP]
    uint32_t* Bs  = As + 128 * GP;
    uint32_t* Asl = Bs + 128 * GP;       // lo parts (SPLIT only)
    uint32_t* Bsl = Asl + 128 * GP;

    const int tid  = threadIdx.x;
    const int lane = tid & 31;
    const int g    = lane >> 2;
    const int tg   = lane & 3;
    const int wid  = tid >> 5;
    const int wr   = (wid & 1) * 64;
    const int wc   = (wid >> 1) * 32;
    const int brow = blockIdx.y * 128;
    const int bcol = blockIdx.x * 128;

    const float* Ab = A  + (size_t)brow * K;
    const float* Bb = Bt + (size_t)bcol * K;
    const int nch = K >> 5;

    float d[4][4][4];
    #pragma unroll
    for (int mt = 0; mt < 4; mt++)
        #pragma unroll
        for (int nt = 0; nt < 4; nt++)
            #pragma unroll
            for (int i = 0; i < 4; i++) d[mt][nt][i] = 0.0f;

    float4 pa[4], pb[4];
    #pragma unroll
    for (int l = 0; l < 4; l++) {
        int e = tid + l * 256;
        int row = e >> 3, c4 = (e & 7) << 2;
        pa[l] = *(const float4*)(Ab + (size_t)row * K + c4);
        pb[l] = *(const float4*)(Bb + (size_t)row * K + c4);
    }

    for (int c = 0; c < nch; ++c) {
        __syncthreads();
        #pragma unroll
        for (int l = 0; l < 4; l++) {
            int e = tid + l * 256;
            int row = e >> 3, c4 = (e & 7) << 2;
            uint32_t* ap = As + row * GP + c4;
            uint32_t* bp = Bs + row * GP + c4;
            uint4 ha = { tf32r(pa[l].x), tf32r(pa[l].y), tf32r(pa[l].z), tf32r(pa[l].w) };
            uint4 hb = { tf32r(pb[l].x), tf32r(pb[l].y), tf32r(pb[l].z), tf32r(pb[l].w) };
            *(uint4*)ap = ha;
            *(uint4*)bp = hb;
            if (SPLIT) {
                uint4 la = { tf32r(pa[l].x - __uint_as_float(ha.x)),
                             tf32r(pa[l].y - __uint_as_float(ha.y)),
                             tf32r(pa[l].z - __uint_as_float(ha.z)),
                             tf32r(pa[l].w - __uint_as_float(ha.w)) };
                uint4 lb = { tf32r(pb[l].x - __uint_as_float(hb.x)),
                             tf32r(pb[l].y - __uint_as_float(hb.y)),
                             tf32r(pb[l].z - __uint_as_float(hb.z)),
                             tf32r(pb[l].w - __uint_as_float(hb.w)) };
                *(uint4*)(Asl + row * GP + c4) = la;
                *(uint4*)(Bsl + row * GP + c4) = lb;
            }
        }
        __syncthreads();

        if (c + 1 < nch) {
            const int k0 = (c + 1) << 5;
            #pragma unroll
            for (int l = 0; l < 4; l++) {
                int e = tid + l * 256;
                int row = e >> 3, c4 = (e & 7) << 2;
                pa[l] = *(const float4*)(Ab + (size_t)row * K + k0 + c4);
                pb[l] = *(const float4*)(Bb + (size_t)row * K + k0 + c4);
            }
        }

        #pragma unroll
        for (int ks = 0; ks < 4; ks++) {
            const int k8 = ks * 8;
            uint32_t af[4][4], bf[4][2];
            #pragma unroll
            for (int mt = 0; mt < 4; mt++) {
                const uint32_t* ap = As + (wr + mt * 16 + g) * GP + k8 + tg;
                af[mt][0] = ap[0];
                af[mt][2] = ap[4];
                af[mt][1] = ap[8 * GP];
                af[mt][3] = ap[8 * GP + 4];
            }
            #pragma unroll
            for (int nt = 0; nt < 4; nt++) {
                const uint32_t* bp = Bs + (wc + nt * 8 + g) * GP + k8 + tg;
                bf[nt][0] = bp[0];
                bf[nt][1] = bp[4];
            }
            #pragma unroll
            for (int mt = 0; mt < 4; mt++)
                #pragma unroll
                for (int nt = 0; nt < 4; nt++)
                    mma1688(d[mt][nt], af[mt], bf[nt]);

            if (SPLIT) {
                uint32_t bl[4][2];
                #pragma unroll
                for (int nt = 0; nt < 4; nt++) {
                    const uint32_t* bp = Bsl + (wc + nt * 8 + g) * GP + k8 + tg;
                    bl[nt][0] = bp[0];
                    bl[nt][1] = bp[4];
                }
                #pragma unroll
                for (int mt = 0; mt < 4; mt++)
                    #pragma unroll
                    for (int nt = 0; nt < 4; nt++)
                        mma1688(d[mt][nt], af[mt], bl[nt]);
                uint32_t al[4][4];
                #pragma unroll
                for (int mt = 0; mt < 4; mt++) {
                    const uint32_t* ap = Asl + (wr + mt * 16 + g) * GP + k8 + tg;
                    al[mt][0] = ap[0];
                    al[mt][2] = ap[4];
                    al[mt][1] = ap[8 * GP];
                    al[mt][3] = ap[8 * GP + 4];
                }
                #pragma unroll
                for (int mt = 0; mt < 4; mt++)
                    #pragma unroll
                    for (int nt = 0; nt < 4; nt++)
                        mma1688(d[mt][nt], al[mt], bf[nt]);
            }
        }
    }

    #pragma unroll
    for (int mt = 0; mt < 4; mt++) {
        const int row0 = brow + wr + mt * 16 + g;
        #pragma unroll
        for (int nt = 0; nt < 4; nt++) {
            const int col = bcol + wc + nt * 8 + 2 * tg;
            float2 v0 = { d[mt][nt][0], d[mt][nt][1] };
            float2 v1 = { d[mt][nt][2], d[mt][nt][3] };
            if (bias) {
                float2 bv = *(const float2*)(bias + col);
                v0.x += bv.x; v0.y += bv.y;
                v1.x += bv.x; v1.y += bv.y;
            }
            *(float2*)(C + (size_t)row0 * Ntot + col)       = v0;
            *(float2*)(C + (size_t)(row0 + 8) * Ntot + col) = v1;
        }
    }
}

// ============== flash attention on tensor cores (tf32 mma) =================
// Block: (b, h, 64 q-rows). 256 thr = 8 warps: qg = wid&3 (16 q rows each),
// kh = wid>>2 (key half for QK / dv half for PV).
// Rank-1 bias trick: logits = (q*s + pos)·k  [tf32 mma]  +  relb·k  [exact fp32].
#define QP 68    // pitch for Qs/Ks(P) tiles
#define VP 200   // pitch for Vs tile

__global__ __launch_bounds__(256, 2)
void attn_mma(const float* __restrict__ qp, const float* __restrict__ kp,
              const float* __restrict__ vp, const float* __restrict__ pos,
              const float* __restrict__ relb, float* __restrict__ out)
{
    extern __shared__ uint32_t smw[];
    uint32_t* Qs  = smw;                 // 64 x QP (tf32)
    uint32_t* Ks  = Qs + 64 * QP;        // K tile (tf32), reused as P tile
    uint32_t* Vs  = Ks + 64 * QP;        // 64 x VP (tf32)
    float* rbs    = (float*)(Vs + 64 * VP);   // 64
    float* cs     = rbs + 64;                 // 64
    float* mrow   = cs + 64;                  // 64
    float* lrow   = mrow + 64;                // 64
    float* srow   = lrow + 64;                // 64
    float* pmax   = srow + 64;                // 2 x 64
    float* psum   = pmax + 128;               // 2 x 64

    const int tid  = threadIdx.x;
    const int lane = tid & 31;
    const int g    = lane >> 2;
    const int tg   = lane & 3;
    const int wid  = tid >> 5;
    const int qg   = wid & 3;            // q-row group (16 rows)
    const int kh   = wid >> 1 >> 1;      // 0/1
    const int b    = blockIdx.z, h = blockIdx.y;
    const int q0   = blockIdx.x * 64;

    const float* qb = qp + (size_t)b * NSEQ * QKW + h * DK;
    const float* kb = kp + (size_t)b * NSEQ * QKW + h * DK;
    const float* vb = vp + (size_t)b * NSEQ * VW  + h * DV;
    const float* pb = pos + (size_t)h * NSEQ * DK;

    // Q tile: (q*scale + pos) as tf32. relb handled exactly via cs.
    #pragma unroll
    for (int l = 0; l < 4; l++) {
        int e = tid + l * 256;
        int r = e >> 4, d = (e & 15) << 2;
        float4 qv = *(const float4*)(qb + (size_t)(q0 + r) * QKW + d);
        float4 pv = *(const float4*)(pb + (size_t)(q0 + r) * DK + d);
        uint4 o;
        o.x = tf32r(qv.x * QSCALE + pv.x);
        o.y = tf32r(qv.y * QSCALE + pv.y);
        o.z = tf32r(qv.z * QSCALE + pv.z);
        o.w = tf32r(qv.w * QSCALE + pv.w);
        *(uint4*)(Qs + r * QP + d) = o;
    }
    if (tid < 64) {
        rbs[tid]  = relb[h * DK + tid];
        mrow[tid] = -1e30f;
        lrow[tid] = 0.0f;
    }

    float oa[12][4];
    #pragma unroll
    for (int nt = 0; nt < 12; nt++)
        #pragma unroll
        for (int i = 0; i < 4; i++) oa[nt][i] = 0.0f;

    for (int j0 = 0; j0 < NSEQ; j0 += 64) {
        __syncthreads();   // previous P/V fully consumed

        // K tile (tf32)
        #pragma unroll
        for (int l = 0; l < 4; l++) {
            int e = tid + l * 256;
            int r = e >> 4, d = (e & 15) << 2;
            float4 kv = *(const float4*)(kb + (size_t)(j0 + r) * QKW + d);
            uint4 o = { tf32r(kv.x), tf32r(kv.y), tf32r(kv.z), tf32r(kv.w) };
            *(uint4*)(Ks + r * QP + d) = o;
        }
        // V tile (tf32)
        #pragma unroll
        for (int l = 0; l < 12; l++) {
            int e = tid + l * 256;
            int r = e / 48, c4 = (e % 48) << 2;
            float4 vv = *(const float4*)(vb + (size_t)(j0 + r) * VW + c4);
            uint4 o = { tf32r(vv.x), tf32r(vv.y), tf32r(vv.z), tf32r(vv.w) };
            *(uint4*)(Vs + r * VP + c4) = o;
        }
        // exact fp32 c_j = relb . k_j
        if (tid < 64) {
            const float4* kr = (const float4*)(kb + (size_t)(j0 + tid) * QKW);
            float c = 0.0f;
            #pragma unroll
            for (int d4 = 0; d4 < 16; d4++) {
                float4 kv = kr[d4];
                float4 rv = *(const float4*)(rbs + d4 * 4);
                c += rv.x * kv.x + rv.y * kv.y + rv.z * kv.z + rv.w * kv.w;
            }
            cs[tid] = c;
        }
        __syncthreads();

        // S = Qb @ K^T : warp -> 16 q rows x 32 keys (4 n-tiles)
        float s[4][4];
        #pragma unroll
        for (int nt = 0; nt < 4; nt++)
            #pragma unroll
            for (int i = 0; i < 4; i++) s[nt][i] = 0.0f;
        #pragma unroll
        for (int ks = 0; ks < 8; ks++) {
            const int k8 = ks * 8;
            uint32_t af[4];
            const uint32_t* ap = Qs + (qg * 16 + g) * QP + k8 + tg;
            af[0] = ap[0];
            af[1] = ap[8 * QP];
            af[2] = ap[4];
            af[3] = ap[8 * QP + 4];
            #pragma unroll
            for (int nt = 0; nt < 4; nt++) {
                const uint32_t* bp = Ks + (kh * 32 + nt * 8 + g) * QP + k8 + tg;
                uint32_t bf[2] = { bp[0], bp[4] };
                mma1688(s[nt], af, bf);
            }
        }
        // add exact bias term
        #pragma unroll
        for (int nt = 0; nt < 4; nt++) {
            const int col0 = kh * 32 + nt * 8 + 2 * tg;
            float c0 = cs[col0], c1 = cs[col0 + 1];
            s[nt][0] += c0; s[nt][1] += c1;
            s[nt][2] += c0; s[nt][3] += c1;
        }

        // row max (rows g and g+8 of this warp's 16-row group)
        float mlo = -1e30f, mhi = -1e30f;
        #pragma unroll
        for (int nt = 0; nt < 4; nt++) {
            mlo = fmaxf(mlo, fmaxf(s[nt][0], s[nt][1]));
            mhi = fmaxf(mhi, fmaxf(s[nt][2], s[nt][3]));
        }
        #pragma unroll
        for (int o = 1; o <= 2; o <<= 1) {
            mlo = fmaxf(mlo, __shfl_xor_sync(0xffffffffu, mlo, o));
            mhi = fmaxf(mhi, __shfl_xor_sync(0xffffffffu, mhi, o));
        }
        if (tg == 0) {
            pmax[kh * 64 + qg * 16 + g]     = mlo;
            pmax[kh * 64 + qg * 16 + g + 8] = mhi;
        }
        __syncthreads();   // QK reads of Ks done; pmax visible

        if (tid < 64) {
            float mo = mrow[tid];
            float mn = fmaxf(mo, fmaxf(pmax[tid], pmax[64 + tid]));
            srow[tid] = __expf(mo - mn);
            mrow[tid] = mn;
        }
        __syncthreads();   // mrow/srow visible; Ks safe to overwrite with P

        // exp, write P (tf32) into Ks, partial row sums
        const float mloN = mrow[qg * 16 + g];
        const float mhiN = mrow[qg * 16 + g + 8];
        float slo = 0.0f, shi = 0.0f;
        #pragma unroll
        for (int nt = 0; nt < 4; nt++) {
            const int col = kh * 32 + nt * 8 + 2 * tg;
            float p0 = __expf(s[nt][0] - mloN);
            float p1 = __expf(s[nt][1] - mloN);
            float p2 = __expf(s[nt][2] - mhiN);
            float p3 = __expf(s[nt][3] - mhiN);
            uint32_t* plo = Ks + (qg * 16 + g) * QP + col;
            uint32_t* phi = Ks + (qg * 16 + g + 8) * QP + col;
            plo[0] = tf32r(p0); plo[1] = tf32r(p1);
            phi[0] = tf32r(p2); phi[1] = tf32r(p3);
            slo += p0 + p1;
            shi += p2 + p3;
        }
        #pragma unroll
        for (int o = 1; o <= 2; o <<= 1) {
            slo += __shfl_xor_sync(0xffffffffu, slo, o);
            shi += __shfl_xor_sync(0xffffffffu, shi, o);
        }
        if (tg == 0) {
            psum[kh * 64 + qg * 16 + g]     = slo;
            psum[kh * 64 + qg * 16 + g + 8] = shi;
        }

        // rescale accumulators (srow ready)
        {
            const float sc0 = srow[qg * 16 + g];
            const float sc1 = srow[qg * 16 + g + 8];
            #pragma unroll
            for (int nt = 0; nt < 12; nt++) {
                oa[nt][0] *= sc0; oa[nt][1] *= sc0;
                oa[nt][2] *= sc1; oa[nt][3] *= sc1;
            }
        }
        __syncthreads();   // P + psum visible

        if (tid < 64)
            lrow[tid] = lrow[tid] * srow[tid] + psum[tid] + psum[64 + tid];

        // O += P @ V : warp -> 16 q rows x 96 dv cols (kh half)
        #pragma unroll
        for (int ks = 0; ks < 8; ks++) {
            const int k8 = ks * 8;
            uint32_t af[4];
            const uint32_t* ap = Ks + (qg * 16 + g) * QP + k8 + tg;
            af[0] = ap[0];
            af[1] = ap[8 * QP];
            af[2] = ap[4];
            af[3] = ap[8 * QP + 4];
            #pragma unroll
            for (int nt = 0; nt < 12; nt++) {
                const uint32_t* bp = Vs + (k8 + tg) * VP + kh * 96 + nt * 8 + g;
                uint32_t bf[2] = { bp[0], bp[4 * VP] };
                mma1688(oa[nt], af, bf);
            }
        }
    }

    __syncthreads();   // final lrow update visible
    {
        const float ilo = 1.0f / lrow[qg * 16 + g];
        const float ihi = 1.0f / lrow[qg * 16 + g + 8];
        const size_t rlo = (size_t)(b * NSEQ + q0 + qg * 16 + g) * VW;
        const size_t rhi = rlo + 8 * VW;
        #pragma unroll
        for (int nt = 0; nt < 12; nt++) {
            const int col = h * DV + kh * 96 + nt * 8 + 2 * tg;
            float2 v0 = { oa[nt][0] * ilo, oa[nt][1] * ilo };
            float2 v1 = { oa[nt][2] * ihi, oa[nt][3] * ihi };
            *(float2*)(out + rlo + col) = v0;
            *(float2*)(out + rhi + col) = v1;
        }
    }
}

// ---------------------------------------------------------------------------
extern "C" void kernel_launch(void* const* d_in, const int* in_sizes, int n_in,
                              void* d_out, int out_size)
{
    (void)in_sizes; (void)n_in; (void)out_size;
    const float* x   = (const float*)d_in[0];
    const float* Wq  = (const float*)d_in[1];
    const float* Wk  = (const float*)d_in[2];
    const float* Wv  = (const float*)d_in[3];
    const float* Wo  = (const float*)d_in[4];
    const float* bo  = (const float*)d_in[5];
    const float* pos = (const float*)d_in[6];
    const float* rb  = (const float*)d_in[7];
    float* out = (float*)d_out;

    float *gq, *gk, *gv, *gao, *wqT, *wkT, *wvT, *woT;
    cudaGetSymbolAddress((void**)&gq,  g_q);
    cudaGetSymbolAddress((void**)&gk,  g_k);
    cudaGetSymbolAddress((void**)&gv,  g_v);
    cudaGetSymbolAddress((void**)&gao, g_ao);
    cudaGetSymbolAddress((void**)&wqT, g_wqT);
    cudaGetSymbolAddress((void**)&wkT, g_wkT);
    cudaGetSymbolAddress((void**)&wvT, g_wvT);
    cudaGetSymbolAddress((void**)&woT, g_woT);

    // attn smem: Qs + Ks + Vs (u32) + 9*64 floats of stats
    const int attn_smem = (64 * QP * 2 + 64 * VP) * 4 + (64 * 5 + 128 * 2) * 4;
    const int gsmem0 = 2 * 128 * GP * 4;
    const int gsmem1 = 4 * 128 * GP * 4;
    cudaFuncSetAttribute(attn_mma,    cudaFuncAttributeMaxDynamicSharedMemorySize, attn_smem);
    cudaFuncSetAttribute(gemm_mma<0>, cudaFuncAttributeMaxDynamicSharedMemorySize, gsmem0);
    cudaFuncSetAttribute(gemm_mma<1>, cudaFuncAttributeMaxDynamicSharedMemorySize, gsmem1);

    dim3 tb(32, 8);
    transpose_k<<<dim3(QKW / 32,  DIMM / 32), tb>>>(Wq, wqT, DIMM, QKW);
    transpose_k<<<dim3(QKW / 32,  DIMM / 32), tb>>>(Wk, wkT, DIMM, QKW);
    transpose_k<<<dim3(VW  / 32,  DIMM / 32), tb>>>(Wv, wvT, DIMM, VW);
    transpose_k<<<dim3(DIMM / 32, VW  / 32),  tb>>>(Wo, woT, VW,  DIMM);

    gemm_mma<0><<<dim3(QKW / 128, MROWS / 128), 256, gsmem0>>>(x, wqT, gq, nullptr, MROWS, QKW, DIMM);
    gemm_mma<1><<<dim3(QKW / 128, MROWS / 128), 256, gsmem1>>>(x, wkT, gk, nullptr, MROWS, QKW, DIMM);
    gemm_mma<0><<<dim3(VW  / 128, MROWS / 128), 256, gsmem0>>>(x, wvT, gv, nullptr, MROWS, VW,  DIMM);

    attn_mma<<<dim3(NSEQ / 64, HEADS, BATCH), 256, attn_smem>>>(gq, gk, gv, pos, rb, gao);

    gemm_mma<0><<<dim3(DIMM / 128, MROWS / 128), 256, gsmem0>>>(gao, woT, out, bo, MROWS, DIMM, VW);
}

// round 15
// speedup vs baseline: 2.2132x; 1.0003x over previous
#include <cuda_runtime.h>
#include <cuda_bf16.h>
#include <cstdint>

typedef unsigned long long u64t;

#define BATCH 2
#define NSEQ  2048
#define DIMM  1536
#define HEADS 8
#define DK    64
#define DV    192
#define QSCALE 0.125f

#define MROWS (BATCH*NSEQ)          // 4096
#define QKW   (HEADS*DK)            // 512
#define VW    (HEADS*DV)            // 1536

// ---- static device scratch (allocation-free) ----
__device__ float g_q  [MROWS * QKW];
__device__ float g_k  [MROWS * QKW];
__device__ float g_v  [MROWS * VW];
__device__ float g_ao [MROWS * VW];
__device__ float g_wqT[QKW * DIMM];
__device__ float g_wkT[QKW * DIMM];
__device__ float g_wvT[VW  * DIMM];
__device__ float g_woT[DIMM * DIMM];

// =========================== common helpers ================================
__device__ __forceinline__ uint32_t tf32r(float x) {
    uint32_t r; asm("cvt.rna.tf32.f32 %0, %1;" : "=r"(r) : "f"(x)); return r;
}

__device__ __forceinline__ void mma1688(float* d, const uint32_t* a, const uint32_t* b) {
    asm volatile(
        "mma.sync.aligned.m16n8k8.row.col.f32.tf32.tf32.f32 "
        "{%0,%1,%2,%3}, {%4,%5,%6,%7}, {%8,%9}, {%0,%1,%2,%3};"
        : "+f"(d[0]), "+f"(d[1]), "+f"(d[2]), "+f"(d[3])
        : "r"(a[0]), "r"(a[1]), "r"(a[2]), "r"(a[3]), "r"(b[0]), "r"(b[1]));
}

// ======================= transpose (B -> K-major) ==========================
__global__ void transpose_k(const float* __restrict__ src, float* __restrict__ dst,
                            int R, int C)
{
    __shared__ float t[32][33];
    const int c  = blockIdx.x * 32 + threadIdx.x;
    const int r0 = blockIdx.y * 32;
    #pragma unroll
    for (int j = threadIdx.y; j < 32; j += 8)
        t[j][threadIdx.x] = src[(size_t)(r0 + j) * C + c];
    __syncthreads();
    const int rr  = r0 + threadIdx.x;
    const int cc0 = blockIdx.x * 32;
    #pragma unroll
    for (int j = threadIdx.y; j < 32; j += 8)
        dst[(size_t)(cc0 + j) * R + rr] = t[threadIdx.x][j];
}

// ===================== tensor-core tf32 GEMM (mma.sync) ====================
#define GP 36   // smem pitch in floats

template<int SPLIT>
__global__ __launch_bounds__(256)
void gemm_mma(const float* __restrict__ A, const float* __restrict__ Bt,
              float* __restrict__ C, const float* __restrict__ bias,
              int M, int Ntot, int K)
{
    extern __shared__ uint32_t smu[];
    uint32_t* As  = smu;                 // [128][GP]
    uint32_t* Bs  = As + 128 * GP;
    uint32_t* Asl = Bs + 128 * GP;       // lo parts (SPLIT only)
    uint32_t* Bsl = Asl + 128 * GP;

    const int tid  = threadIdx.x;
    const int lane = tid & 31;
    const int g    = lane >> 2;
    const int tg   = lane & 3;
    const int wid  = tid >> 5;
    const int wr   = (wid & 1) * 64;
    const int wc   = (wid >> 1) * 32;
    const int brow = blockIdx.y * 128;
    const int bcol = blockIdx.x * 128;

    const float* Ab = A  + (size_t)brow * K;
    const float* Bb = Bt + (size_t)bcol * K;
    const int nch = K >> 5;

    float d[4][4][4];
    #pragma unroll
    for (int mt = 0; mt < 4; mt++)
        #pragma unroll
        for (int nt = 0; nt < 4; nt++)
            #pragma unroll
            for (int i = 0; i < 4; i++) d[mt][nt][i] = 0.0f;

    float4 pa[4], pb[4];
    #pragma unroll
    for (int l = 0; l < 4; l++) {
        int e = tid + l * 256;
        int row = e >> 3, c4 = (e & 7) << 2;
        pa[l] = *(const float4*)(Ab + (size_t)row * K + c4);
        pb[l] = *(const float4*)(Bb + (size_t)row * K + c4);
    }

    for (int c = 0; c < nch; ++c) {
        __syncthreads();
        #pragma unroll
        for (int l = 0; l < 4; l++) {
            int e = tid + l * 256;
            int row = e >> 3, c4 = (e & 7) << 2;
            uint32_t* ap = As + row * GP + c4;
            uint32_t* bp = Bs + row * GP + c4;
            uint4 ha = { tf32r(pa[l].x), tf32r(pa[l].y), tf32r(pa[l].z), tf32r(pa[l].w) };
            uint4 hb = { tf32r(pb[l].x), tf32r(pb[l].y), tf32r(pb[l].z), tf32r(pb[l].w) };
            *(uint4*)ap = ha;
            *(uint4*)bp = hb;
            if (SPLIT) {
                uint4 la = { tf32r(pa[l].x - __uint_as_float(ha.x)),
                             tf32r(pa[l].y - __uint_as_float(ha.y)),
                             tf32r(pa[l].z - __uint_as_float(ha.z)),
                             tf32r(pa[l].w - __uint_as_float(ha.w)) };
                uint4 lb = { tf32r(pb[l].x - __uint_as_float(hb.x)),
                             tf32r(pb[l].y - __uint_as_float(hb.y)),
                             tf32r(pb[l].z - __uint_as_float(hb.z)),
                             tf32r(pb[l].w - __uint_as_float(hb.w)) };
                *(uint4*)(Asl + row * GP + c4) = la;
                *(uint4*)(Bsl + row * GP + c4) = lb;
            }
        }
        __syncthreads();

        if (c + 1 < nch) {
            const int k0 = (c + 1) << 5;
            #pragma unroll
            for (int l = 0; l < 4; l++) {
                int e = tid + l * 256;
                int row = e >> 3, c4 = (e & 7) << 2;
                pa[l] = *(const float4*)(Ab + (size_t)row * K + k0 + c4);
                pb[l] = *(const float4*)(Bb + (size_t)row * K + k0 + c4);
            }
        }

        #pragma unroll
        for (int ks = 0; ks < 4; ks++) {
            const int k8 = ks * 8;
            uint32_t af[4][4], bf[4][2];
            #pragma unroll
            for (int mt = 0; mt < 4; mt++) {
                const uint32_t* ap = As + (wr + mt * 16 + g) * GP + k8 + tg;
                af[mt][0] = ap[0];
                af[mt][2] = ap[4];
                af[mt][1] = ap[8 * GP];
                af[mt][3] = ap[8 * GP + 4];
            }
            #pragma unroll
            for (int nt = 0; nt < 4; nt++) {
                const uint32_t* bp = Bs + (wc + nt * 8 + g) * GP + k8 + tg;
                bf[nt][0] = bp[0];
                bf[nt][1] = bp[4];
            }
            #pragma unroll
            for (int mt = 0; mt < 4; mt++)
                #pragma unroll
                for (int nt = 0; nt < 4; nt++)
                    mma1688(d[mt][nt], af[mt], bf[nt]);

            if (SPLIT) {
                uint32_t bl[4][2];
                #pragma unroll
                for (int nt = 0; nt < 4; nt++) {
                    const uint32_t* bp = Bsl + (wc + nt * 8 + g) * GP + k8 + tg;
                    bl[nt][0] = bp[0];
                    bl[nt][1] = bp[4];
                }
                #pragma unroll
                for (int mt = 0; mt < 4; mt++)
                    #pragma unroll
                    for (int nt = 0; nt < 4; nt++)
                        mma1688(d[mt][nt], af[mt], bl[nt]);
                uint32_t al[4][4];
                #pragma unroll
                for (int mt = 0; mt < 4; mt++) {
                    const uint32_t* ap = Asl + (wr + mt * 16 + g) * GP + k8 + tg;
                    al[mt][0] = ap[0];
                    al[mt][2] = ap[4];
                    al[mt][1] = ap[8 * GP];
                    al[mt][3] = ap[8 * GP + 4];
                }
                #pragma unroll
                for (int mt = 0; mt < 4; mt++)
                    #pragma unroll
                    for (int nt = 0; nt < 4; nt++)
                        mma1688(d[mt][nt], al[mt], bf[nt]);
            }
        }
    }

    #pragma unroll
    for (int mt = 0; mt < 4; mt++) {
        const int row0 = brow + wr + mt * 16 + g;
        #pragma unroll
        for (int nt = 0; nt < 4; nt++) {
            const int col = bcol + wc + nt * 8 + 2 * tg;
            float2 v0 = { d[mt][nt][0], d[mt][nt][1] };
            float2 v1 = { d[mt][nt][2], d[mt][nt][3] };
            if (bias) {
                float2 bv = *(const float2*)(bias + col);
                v0.x += bv.x; v0.y += bv.y;
                v1.x += bv.x; v1.y += bv.y;
            }
            *(float2*)(C + (size_t)row0 * Ntot + col)       = v0;
            *(float2*)(C + (size_t)(row0 + 8) * Ntot + col) = v1;
        }
    }
}

// ============== flash attention on tensor cores (tf32 mma) =================
// Block: (b, h, 64 q-rows). 256 thr = 8 warps: qg = wid&3 (16 q rows each),
// kh = wid>>2 (key half for QK / dv half for PV).
// Rank-1 bias trick: logits = (q*s + pos)·k  [tf32 mma]  +  relb·k  [exact fp32].
#define QP 68    // pitch for Qs/Ks(P) tiles
#define VP 200   // pitch for Vs tile

__global__ __launch_bounds__(256, 2)
void attn_mma(const float* __restrict__ qp, const float* __restrict__ kp,
              const float* __restrict__ vp, const float* __restrict__ pos,
              const float* __restrict__ relb, float* __restrict__ out)
{
    extern __shared__ uint32_t smw[];
    uint32_t* Qs  = smw;                 // 64 x QP (tf32)
    uint32_t* Ks  = Qs + 64 * QP;        // K tile (tf32), reused as P tile
    uint32_t* Vs  = Ks + 64 * QP;        // 64 x VP (tf32)
    float* rbs    = (float*)(Vs + 64 * VP);   // 64
    float* cs     = rbs + 64;                 // 64
    float* mrow   = cs + 64;                  // 64
    float* lrow   = mrow + 64;                // 64
    float* srow   = lrow + 64;                // 64
    float* pmax   = srow + 64;                // 2 x 64
    float* psum   = pmax + 128;               // 2 x 64

    const int tid  = threadIdx.x;
    const int lane = tid & 31;
    const int g    = lane >> 2;
    const int tg   = lane & 3;
    const int wid  = tid >> 5;
    const int qg   = wid & 3;            // q-row group (16 rows)
    const int kh   = wid >> 1 >> 1;      // 0/1
    const int b    = blockIdx.z, h = blockIdx.y;
    const int q0   = blockIdx.x * 64;

    const float* qb = qp + (size_t)b * NSEQ * QKW + h * DK;
    const float* kb = kp + (size_t)b * NSEQ * QKW + h * DK;
    const float* vb = vp + (size_t)b * NSEQ * VW  + h * DV;
    const float* pb = pos + (size_t)h * NSEQ * DK;

    // Q tile: (q*scale + pos) as tf32. relb handled exactly via cs.
    #pragma unroll
    for (int l = 0; l < 4; l++) {
        int e = tid + l * 256;
        int r = e >> 4, d = (e & 15) << 2;
        float4 qv = *(const float4*)(qb + (size_t)(q0 + r) * QKW + d);
        float4 pv = *(const float4*)(pb + (size_t)(q0 + r) * DK + d);
        uint4 o;
        o.x = tf32r(qv.x * QSCALE + pv.x);
        o.y = tf32r(qv.y * QSCALE + pv.y);
        o.z = tf32r(qv.z * QSCALE + pv.z);
        o.w = tf32r(qv.w * QSCALE + pv.w);
        *(uint4*)(Qs + r * QP + d) = o;
    }
    if (tid < 64) {
        rbs[tid]  = relb[h * DK + tid];
        mrow[tid] = -1e30f;
        lrow[tid] = 0.0f;
    }

    float oa[12][4];
    #pragma unroll
    for (int nt = 0; nt < 12; nt++)
        #pragma unroll
        for (int i = 0; i < 4; i++) oa[nt][i] = 0.0f;

    for (int j0 = 0; j0 < NSEQ; j0 += 64) {
        __syncthreads();   // previous P/V fully consumed

        // K tile (tf32)
        #pragma unroll
        for (int l = 0; l < 4; l++) {
            int e = tid + l * 256;
            int r = e >> 4, d = (e & 15) << 2;
            float4 kv = *(const float4*)(kb + (size_t)(j0 + r) * QKW + d);
            uint4 o = { tf32r(kv.x), tf32r(kv.y), tf32r(kv.z), tf32r(kv.w) };
            *(uint4*)(Ks + r * QP + d) = o;
        }
        // V tile (tf32)
        #pragma unroll
        for (int l = 0; l < 12; l++) {
            int e = tid + l * 256;
            int r = e / 48, c4 = (e % 48) << 2;
            float4 vv = *(const float4*)(vb + (size_t)(j0 + r) * VW + c4);
            uint4 o = { tf32r(vv.x), tf32r(vv.y), tf32r(vv.z), tf32r(vv.w) };
            *(uint4*)(Vs + r * VP + c4) = o;
        }
        // exact fp32 c_j = relb . k_j
        if (tid < 64) {
            const float4* kr = (const float4*)(kb + (size_t)(j0 + tid) * QKW);
            float c = 0.0f;
            #pragma unroll
            for (int d4 = 0; d4 < 16; d4++) {
                float4 kv = kr[d4];
                float4 rv = *(const float4*)(rbs + d4 * 4);
                c += rv.x * kv.x + rv.y * kv.y + rv.z * kv.z + rv.w * kv.w;
            }
            cs[tid] = c;
        }
        __syncthreads();

        // S = Qb @ K^T : warp -> 16 q rows x 32 keys (4 n-tiles)
        float s[4][4];
        #pragma unroll
        for (int nt = 0; nt < 4; nt++)
            #pragma unroll
            for (int i = 0; i < 4; i++) s[nt][i] = 0.0f;
        #pragma unroll
        for (int ks = 0; ks < 8; ks++) {
            const int k8 = ks * 8;
            uint32_t af[4];
            const uint32_t* ap = Qs + (qg * 16 + g) * QP + k8 + tg;
            af[0] = ap[0];
            af[1] = ap[8 * QP];
            af[2] = ap[4];
            af[3] = ap[8 * QP + 4];
            #pragma unroll
            for (int nt = 0; nt < 4; nt++) {
                const uint32_t* bp = Ks + (kh * 32 + nt * 8 + g) * QP + k8 + tg;
                uint32_t bf[2] = { bp[0], bp[4] };
                mma1688(s[nt], af, bf);
            }
        }
        // add exact bias term
        #pragma unroll
        for (int nt = 0; nt < 4; nt++) {
            const int col0 = kh * 32 + nt * 8 + 2 * tg;
            float c0 = cs[col0], c1 = cs[col0 + 1];
            s[nt][0] += c0; s[nt][1] += c1;
            s[nt][2] += c0; s[nt][3] += c1;
        }

        // row max (rows g and g+8 of this warp's 16-row group)
        float mlo = -1e30f, mhi = -1e30f;
        #pragma unroll
        for (int nt = 0; nt < 4; nt++) {
            mlo = fmaxf(mlo, fmaxf(s[nt][0], s[nt][1]));
            mhi = fmaxf(mhi, fmaxf(s[nt][2], s[nt][3]));
        }
        #pragma unroll
        for (int o = 1; o <= 2; o <<= 1) {
            mlo = fmaxf(mlo, __shfl_xor_sync(0xffffffffu, mlo, o));
            mhi = fmaxf(mhi, __shfl_xor_sync(0xffffffffu, mhi, o));
        }
        if (tg == 0) {
            pmax[kh * 64 + qg * 16 + g]     = mlo;
            pmax[kh * 64 + qg * 16 + g + 8] = mhi;
        }
        __syncthreads();   // QK reads of Ks done; pmax visible

        if (tid < 64) {
            float mo = mrow[tid];
            float mn = fmaxf(mo, fmaxf(pmax[tid], pmax[64 + tid]));
            srow[tid] = __expf(mo - mn);
            mrow[tid] = mn;
        }
        __syncthreads();   // mrow/srow visible; Ks safe to overwrite with P

        // exp, write P (tf32) into Ks, partial row sums
        const float mloN = mrow[qg * 16 + g];
        const float mhiN = mrow[qg * 16 + g + 8];
        float slo = 0.0f, shi = 0.0f;
        #pragma unroll
        for (int nt = 0; nt < 4; nt++) {
            const int col = kh * 32 + nt * 8 + 2 * tg;
            float p0 = __expf(s[nt][0] - mloN);
            float p1 = __expf(s[nt][1] - mloN);
            float p2 = __expf(s[nt][2] - mhiN);
            float p3 = __expf(s[nt][3] - mhiN);
            uint32_t* plo = Ks + (qg * 16 + g) * QP + col;
            uint32_t* phi = Ks + (qg * 16 + g + 8) * QP + col;
            plo[0] = tf32r(p0); plo[1] = tf32r(p1);
            phi[0] = tf32r(p2); phi[1] = tf32r(p3);
            slo += p0 + p1;
            shi += p2 + p3;
        }
        #pragma unroll
        for (int o = 1; o <= 2; o <<= 1) {
            slo += __shfl_xor_sync(0xffffffffu, slo, o);
            shi += __shfl_xor_sync(0xffffffffu, shi, o);
        }
        if (tg == 0) {
            psum[kh * 64 + qg * 16 + g]     = slo;
            psum[kh * 64 + qg * 16 + g + 8] = shi;
        }

        // rescale accumulators (srow ready)
        {
            const float sc0 = srow[qg * 16 + g];
            const float sc1 = srow[qg * 16 + g + 8];
            #pragma unroll
            for (int nt = 0; nt < 12; nt++) {
                oa[nt][0] *= sc0; oa[nt][1] *= sc0;
                oa[nt][2] *= sc1; oa[nt][3] *= sc1;
            }
        }
        __syncthreads();   // P + psum visible

        if (tid < 64)
            lrow[tid] = lrow[tid] * srow[tid] + psum[tid] + psum[64 + tid];

        // O += P @ V : warp -> 16 q rows x 96 dv cols (kh half)
        #pragma unroll
        for (int ks = 0; ks < 8; ks++) {
            const int k8 = ks * 8;
            uint32_t af[4];
            const uint32_t* ap = Ks + (qg * 16 + g) * QP + k8 + tg;
            af[0] = ap[0];
            af[1] = ap[8 * QP];
            af[2] = ap[4];
            af[3] = ap[8 * QP + 4];
            #pragma unroll
            for (int nt = 0; nt < 12; nt++) {
                const uint32_t* bp = Vs + (k8 + tg) * VP + kh * 96 + nt * 8 + g;
                uint32_t bf[2] = { bp[0], bp[4 * VP] };
                mma1688(oa[nt], af, bf);
            }
        }
    }

    __syncthreads();   // final lrow update visible
    {
        const float ilo = 1.0f / lrow[qg * 16 + g];
        const float ihi = 1.0f / lrow[qg * 16 + g + 8];
        const size_t rlo = (size_t)(b * NSEQ + q0 + qg * 16 + g) * VW;
        const size_t rhi = rlo + 8 * VW;
        #pragma unroll
        for (int nt = 0; nt < 12; nt++) {
            const int col = h * DV + kh * 96 + nt * 8 + 2 * tg;
            float2 v0 = { oa[nt][0] * ilo, oa[nt][1] * ilo };
            float2 v1 = { oa[nt][2] * ihi, oa[nt][3] * ihi };
            *(float2*)(out + rlo + col) = v0;
            *(float2*)(out + rhi + col) = v1;
        }
    }
}

// ---------------------------------------------------------------------------
extern "C" void kernel_launch(void* const* d_in, const int* in_sizes, int n_in,
                              void* d_out, int out_size)
{
    (void)in_sizes; (void)n_in; (void)out_size;
    const float* x   = (const float*)d_in[0];
    const float* Wq  = (const float*)d_in[1];
    const float* Wk  = (const float*)d_in[2];
    const float* Wv  = (const float*)d_in[3];
    const float* Wo  = (const float*)d_in[4];
    const float* bo  = (const float*)d_in[5];
    const float* pos = (const float*)d_in[6];
    const float* rb  = (const float*)d_in[7];
    float* out = (float*)d_out;

    float *gq, *gk, *gv, *gao, *wqT, *wkT, *wvT, *woT;
    cudaGetSymbolAddress((void**)&gq,  g_q);
    cudaGetSymbolAddress((void**)&gk,  g_k);
    cudaGetSymbolAddress((void**)&gv,  g_v);
    cudaGetSymbolAddress((void**)&gao, g_ao);
    cudaGetSymbolAddress((void**)&wqT, g_wqT);
    cudaGetSymbolAddress((void**)&wkT, g_wkT);
    cudaGetSymbolAddress((void**)&wvT, g_wvT);
    cudaGetSymbolAddress((void**)&woT, g_woT);

    // attn smem: Qs + Ks + Vs (u32) + 9*64 floats of stats
    const int attn_smem = (64 * QP * 2 + 64 * VP) * 4 + (64 * 5 + 128 * 2) * 4;
    const int gsmem0 = 2 * 128 * GP * 4;
    const int gsmem1 = 4 * 128 * GP * 4;
    cudaFuncSetAttribute(attn_mma,    cudaFuncAttributeMaxDynamicSharedMemorySize, attn_smem);
    cudaFuncSetAttribute(gemm_mma<0>, cudaFuncAttributeMaxDynamicSharedMemorySize, gsmem0);
    cudaFuncSetAttribute(gemm_mma<1>, cudaFuncAttributeMaxDynamicSharedMemorySize, gsmem1);

    dim3 tb(32, 8);
    transpose_k<<<dim3(QKW / 32,  DIMM / 32), tb>>>(Wq, wqT, DIMM, QKW);
    transpose_k<<<dim3(QKW / 32,  DIMM / 32), tb>>>(Wk, wkT, DIMM, QKW);
    transpose_k<<<dim3(VW  / 32,  DIMM / 32), tb>>>(Wv, wvT, DIMM, VW);
    transpose_k<<<dim3(DIMM / 32, VW  / 32),  tb>>>(Wo, woT, VW,  DIMM);

    gemm_mma<0><<<dim3(QKW / 128, MROWS / 128), 256, gsmem0>>>(x, wqT, gq, nullptr, MROWS, QKW, DIMM);
    gemm_mma<1><<<dim3(QKW / 128, MROWS / 128), 256, gsmem1>>>(x, wkT, gk, nullptr, MROWS, QKW, DIMM);
    gemm_mma<0><<<dim3(VW  / 128, MROWS / 128), 256, gsmem0>>>(x, wvT, gv, nullptr, MROWS, VW,  DIMM);

    attn_mma<<<dim3(NSEQ / 64, HEADS, BATCH), 256, attn_smem>>>(gq, gk, gv, pos, rb, gao);

    gemm_mma<0><<<dim3(DIMM / 128, MROWS / 128), 256, gsmem0>>>(gao, woT, out, bo, MROWS, DIMM, VW);
}

// round 16
// speedup vs baseline: 2.4044x; 1.0864x over previous
#include <cuda_runtime.h>
#include <cuda_bf16.h>
#include <cstdint>

#define BATCH 2
#define NSEQ  2048
#define DIMM  1536
#define HEADS 8
#define DK    64
#define DV    192
#define QSCALE 0.125f

#define MROWS (BATCH*NSEQ)          // 4096
#define QKW   (HEADS*DK)            // 512
#define VW    (HEADS*DV)            // 1536
#define QKVW  (2*QKW + VW)          // 2560 (q | k | v)

// ---- static device scratch (allocation-free) ----
__device__ float g_xt  [MROWS * DIMM];      // x, tf32-rounded
__device__ float g_qkv [MROWS * QKVW];      // fused projections
__device__ float g_ao  [MROWS * VW];        // attn out (tf32-rounded)
__device__ float g_wT  [QKVW * DIMM];       // [Wq|Wk|Wv]^T, tf32
__device__ float g_woT [DIMM * VW];         // Wo^T, tf32
__device__ float g_u   [HEADS * DIMM];      // Wk_h @ relb_h
__device__ float g_c   [HEADS * MROWS];     // exact relb.k via x-route

// =========================== common helpers ================================
__device__ __forceinline__ uint32_t tf32r(float x) {
    uint32_t r; asm("cvt.rna.tf32.f32 %0, %1;" : "=r"(r) : "f"(x)); return r;
}
__device__ __forceinline__ void mma1688(float* d, const uint32_t* a, const uint32_t* b) {
    asm volatile(
        "mma.sync.aligned.m16n8k8.row.col.f32.tf32.tf32.f32 "
        "{%0,%1,%2,%3}, {%4,%5,%6,%7}, {%8,%9}, {%0,%1,%2,%3};"
        : "+f"(d[0]), "+f"(d[1]), "+f"(d[2]), "+f"(d[3])
        : "r"(a[0]), "r"(a[1]), "r"(a[2]), "r"(a[3]), "r"(b[0]), "r"(b[1]));
}

// =================== prep kernels (run once per launch) ====================
// elementwise tf32 rounding (x -> g_xt)
__global__ void cvt_tf32(const float* __restrict__ src, float* __restrict__ dst, int n4)
{
    int i = blockIdx.x * 256 + threadIdx.x;
    if (i < n4) {
        float4 v = ((const float4*)src)[i];
        uint4 o = { tf32r(v.x), tf32r(v.y), tf32r(v.z), tf32r(v.w) };
        ((uint4*)dst)[i] = o;
    }
}

// transpose + tf32 round: src [R, C] -> dst [C, R]
__global__ void transpose_k(const float* __restrict__ src, float* __restrict__ dst,
                            int R, int C)
{
    __shared__ uint32_t t[32][33];
    const int c  = blockIdx.x * 32 + threadIdx.x;
    const int r0 = blockIdx.y * 32;
    #pragma unroll
    for (int j = threadIdx.y; j < 32; j += 8)
        t[j][threadIdx.x] = tf32r(src[(size_t)(r0 + j) * C + c]);
    __syncthreads();
    const int rr  = r0 + threadIdx.x;
    const int cc0 = blockIdx.x * 32;
    #pragma unroll
    for (int j = threadIdx.y; j < 32; j += 8)
        ((uint32_t*)dst)[(size_t)(cc0 + j) * R + rr] = t[threadIdx.x][j];
}

// u[h][d] = sum_i Wk[d, h*64+i] * relb[h*64+i]
__global__ void compute_u(const float* __restrict__ Wk, const float* __restrict__ relb,
                          float* __restrict__ u)
{
    int t = blockIdx.x * 256 + threadIdx.x;
    if (t >= HEADS * DIMM) return;
    int h = t / DIMM, d = t % DIMM;
    float s = 0.0f;
    #pragma unroll 8
    for (int i = 0; i < DK; i++)
        s += Wk[(size_t)d * QKW + h * DK + i] * relb[h * DK + i];
    u[h * DIMM + d] = s;
}

// c[h][m] = x[m,:] . u[h,:]   (exact fp32 rank-8 GEMV)
__global__ __launch_bounds__(256)
void compute_c(const float* __restrict__ x, const float* __restrict__ u,
               float* __restrict__ c)
{
    __shared__ float us[HEADS * DIMM];   // 48 KB
    for (int i = threadIdx.x; i < HEADS * DIMM; i += 256)
        us[i] = u[i];
    __syncthreads();
    const int m = blockIdx.x * 256 + threadIdx.x;
    float acc[HEADS];
    #pragma unroll
    for (int h = 0; h < HEADS; h++) acc[h] = 0.0f;
    const float4* xr = (const float4*)(x + (size_t)m * DIMM);
    for (int d4 = 0; d4 < DIMM / 4; d4++) {
        float4 xv = xr[d4];
        #pragma unroll
        for (int h = 0; h < HEADS; h++) {
            float4 uv = *(const float4*)(us + h * DIMM + d4 * 4);
            acc[h] += xv.x * uv.x + xv.y * uv.y + xv.z * uv.z + xv.w * uv.w;
        }
    }
    #pragma unroll
    for (int h = 0; h < HEADS; h++) c[h * MROWS + m] = acc[h];
}

// ===================== tensor-core tf32 GEMM (mma.sync) ====================
// Inputs already tf32-rounded (no cvt in the hot loop).
// C[M,Ntot] = A[M,K] @ Bt[Ntot,K]^T (+bias). Columns >= round_col are written
// tf32-rounded (for K/V feeding attention's mma directly).
#define GP 36   // smem pitch in floats

__global__ __launch_bounds__(256)
void gemm_mma(const float* __restrict__ A, const float* __restrict__ Bt,
              float* __restrict__ C, const float* __restrict__ bias,
              int M, int Ntot, int K, int round_col)
{
    __shared__ uint32_t As[128 * GP];
    __shared__ uint32_t Bs[128 * GP];

    const int tid  = threadIdx.x;
    const int lane = tid & 31;
    const int g    = lane >> 2;
    const int tg   = lane & 3;
    const int wid  = tid >> 5;
    const int wr   = (wid & 1) * 64;
    const int wc   = (wid >> 1) * 32;
    const int brow = blockIdx.y * 128;
    const int bcol = blockIdx.x * 128;

    const float* Ab = A  + (size_t)brow * K;
    const float* Bb = Bt + (size_t)bcol * K;
    const int nch = K >> 5;

    float d[4][4][4];
    #pragma unroll
    for (int mt = 0; mt < 4; mt++)
        #pragma unroll
        for (int nt = 0; nt < 4; nt++)
            #pragma unroll
            for (int i = 0; i < 4; i++) d[mt][nt][i] = 0.0f;

    uint4 pa[4], pb[4];
    #pragma unroll
    for (int l = 0; l < 4; l++) {
        int e = tid + l * 256;
        int row = e >> 3, c4 = (e & 7) << 2;
        pa[l] = *(const uint4*)(Ab + (size_t)row * K + c4);
        pb[l] = *(const uint4*)(Bb + (size_t)row * K + c4);
    }

    for (int c = 0; c < nch; ++c) {
        __syncthreads();
        #pragma unroll
        for (int l = 0; l < 4; l++) {
            int e = tid + l * 256;
            int row = e >> 3, c4 = (e & 7) << 2;
            *(uint4*)(As + row * GP + c4) = pa[l];
            *(uint4*)(Bs + row * GP + c4) = pb[l];
        }
        __syncthreads();

        if (c + 1 < nch) {
            const int k0 = (c + 1) << 5;
            #pragma unroll
            for (int l = 0; l < 4; l++) {
                int e = tid + l * 256;
                int row = e >> 3, c4 = (e & 7) << 2;
                pa[l] = *(const uint4*)(Ab + (size_t)row * K + k0 + c4);
                pb[l] = *(const uint4*)(Bb + (size_t)row * K + k0 + c4);
            }
        }

        #pragma unroll
        for (int ks = 0; ks < 4; ks++) {
            const int k8 = ks * 8;
            uint32_t af[4][4], bf[4][2];
            #pragma unroll
            for (int mt = 0; mt < 4; mt++) {
                const uint32_t* ap = As + (wr + mt * 16 + g) * GP + k8 + tg;
                af[mt][0] = ap[0];
                af[mt][2] = ap[4];
                af[mt][1] = ap[8 * GP];
                af[mt][3] = ap[8 * GP + 4];
            }
            #pragma unroll
            for (int nt = 0; nt < 4; nt++) {
                const uint32_t* bp = Bs + (wc + nt * 8 + g) * GP + k8 + tg;
                bf[nt][0] = bp[0];
                bf[nt][1] = bp[4];
            }
            #pragma unroll
            for (int mt = 0; mt < 4; mt++)
                #pragma unroll
                for (int nt = 0; nt < 4; nt++)
                    mma1688(d[mt][nt], af[mt], bf[nt]);
        }
    }

    const bool rnd = (bcol >= round_col);
    #pragma unroll
    for (int mt = 0; mt < 4; mt++) {
        const int row0 = brow + wr + mt * 16 + g;
        #pragma unroll
        for (int nt = 0; nt < 4; nt++) {
            const int col = bcol + wc + nt * 8 + 2 * tg;
            float2 v0 = { d[mt][nt][0], d[mt][nt][1] };
            float2 v1 = { d[mt][nt][2], d[mt][nt][3] };
            if (bias) {
                float2 bv = *(const float2*)(bias + col);
                v0.x += bv.x; v0.y += bv.y;
                v1.x += bv.x; v1.y += bv.y;
            }
            if (rnd) {
                v0.x = __uint_as_float(tf32r(v0.x));
                v0.y = __uint_as_float(tf32r(v0.y));
                v1.x = __uint_as_float(tf32r(v1.x));
                v1.y = __uint_as_float(tf32r(v1.y));
            }
            *(float2*)(C + (size_t)row0 * Ntot + col)       = v0;
            *(float2*)(C + (size_t)(row0 + 8) * Ntot + col) = v1;
        }
    }
}

// ============== flash attention on tensor cores (tf32 mma) =================
// qkv rows: [q(512) | k(512) | v(1536)], k/v columns already tf32-rounded.
// logits = (q*s+pos).k [mma] + c_j [exact fp32, precomputed from x].
#define QP 68
#define VP 200

__global__ __launch_bounds__(256, 2)
void attn_mma(const float* __restrict__ qkv, const float* __restrict__ pos,
              const float* __restrict__ cvec, float* __restrict__ out)
{
    extern __shared__ uint32_t smw[];
    uint32_t* Qs  = smw;                 // 64 x QP (tf32)
    uint32_t* Ks  = Qs + 64 * QP;        // K tile, reused as P tile
    uint32_t* Vs  = Ks + 64 * QP;        // 64 x VP
    float* cs     = (float*)(Vs + 64 * VP);   // 64
    float* mrow   = cs + 64;                  // 64
    float* lrow   = mrow + 64;                // 64
    float* srow   = lrow + 64;                // 64
    float* pmax   = srow + 64;                // 2 x 64
    float* psum   = pmax + 128;               // 2 x 64

    const int tid  = threadIdx.x;
    const int lane = tid & 31;
    const int g    = lane >> 2;
    const int tg   = lane & 3;
    const int wid  = tid >> 5;
    const int qg   = wid & 3;
    const int kh   = wid >> 2;
    const int b    = blockIdx.z, h = blockIdx.y;
    const int q0   = blockIdx.x * 64;

    const float* qb = qkv + (size_t)b * NSEQ * QKVW + h * DK;
    const float* kb = qb + QKW;
    const float* vb = qkv + (size_t)b * NSEQ * QKVW + 2 * QKW + h * DV;
    const float* pb = pos + (size_t)h * NSEQ * DK;
    const float* cb = cvec + h * MROWS + b * NSEQ;

    // Q tile: (q*scale + pos) -> tf32
    #pragma unroll
    for (int l = 0; l < 4; l++) {
        int e = tid + l * 256;
        int r = e >> 4, d = (e & 15) << 2;
        float4 qv = *(const float4*)(qb + (size_t)(q0 + r) * QKVW + d);
        float4 pv = *(const float4*)(pb + (size_t)(q0 + r) * DK + d);
        uint4 o;
        o.x = tf32r(qv.x * QSCALE + pv.x);
        o.y = tf32r(qv.y * QSCALE + pv.y);
        o.z = tf32r(qv.z * QSCALE + pv.z);
        o.w = tf32r(qv.w * QSCALE + pv.w);
        *(uint4*)(Qs + r * QP + d) = o;
    }
    if (tid < 64) { mrow[tid] = -1e30f; lrow[tid] = 0.0f; }

    float oa[12][4];
    #pragma unroll
    for (int nt = 0; nt < 12; nt++)
        #pragma unroll
        for (int i = 0; i < 4; i++) oa[nt][i] = 0.0f;

    for (int j0 = 0; j0 < NSEQ; j0 += 64) {
        __syncthreads();   // previous P/V fully consumed

        // K tile (already tf32 bits) — raw copy
        #pragma unroll
        for (int l = 0; l < 4; l++) {
            int e = tid + l * 256;
            int r = e >> 4, d = (e & 15) << 2;
            *(uint4*)(Ks + r * QP + d) =
                *(const uint4*)(kb + (size_t)(j0 + r) * QKVW + d);
        }
        // V tile (already tf32 bits) — raw copy
        #pragma unroll
        for (int l = 0; l < 12; l++) {
            int e = tid + l * 256;
            int r = e / 48, c4 = (e % 48) << 2;
            *(uint4*)(Vs + r * VP + c4) =
                *(const uint4*)(vb + (size_t)(j0 + r) * QKVW + c4);
        }
        // exact bias term for this tile
        if (tid < 64) cs[tid] = cb[j0 + tid];
        __syncthreads();

        // S = Qb @ K^T : warp -> 16 q rows x 32 keys
        float s[4][4];
        #pragma unroll
        for (int nt = 0; nt < 4; nt++)
            #pragma unroll
            for (int i = 0; i < 4; i++) s[nt][i] = 0.0f;
        #pragma unroll
        for (int ks = 0; ks < 8; ks++) {
            const int k8 = ks * 8;
            uint32_t af[4];
            const uint32_t* ap = Qs + (qg * 16 + g) * QP + k8 + tg;
            af[0] = ap[0];
            af[1] = ap[8 * QP];
            af[2] = ap[4];
            af[3] = ap[8 * QP + 4];
            #pragma unroll
            for (int nt = 0; nt < 4; nt++) {
                const uint32_t* bp = Ks + (kh * 32 + nt * 8 + g) * QP + k8 + tg;
                uint32_t bf[2] = { bp[0], bp[4] };
                mma1688(s[nt], af, bf);
            }
        }
        #pragma unroll
        for (int nt = 0; nt < 4; nt++) {
            const int col0 = kh * 32 + nt * 8 + 2 * tg;
            float c0 = cs[col0], c1 = cs[col0 + 1];
            s[nt][0] += c0; s[nt][1] += c1;
            s[nt][2] += c0; s[nt][3] += c1;
        }

        // row max
        float mlo = -1e30f, mhi = -1e30f;
        #pragma unroll
        for (int nt = 0; nt < 4; nt++) {
            mlo = fmaxf(mlo, fmaxf(s[nt][0], s[nt][1]));
            mhi = fmaxf(mhi, fmaxf(s[nt][2], s[nt][3]));
        }
        #pragma unroll
        for (int o = 1; o <= 2; o <<= 1) {
            mlo = fmaxf(mlo, __shfl_xor_sync(0xffffffffu, mlo, o));
            mhi = fmaxf(mhi, __shfl_xor_sync(0xffffffffu, mhi, o));
        }
        if (tg == 0) {
            pmax[kh * 64 + qg * 16 + g]     = mlo;
            pmax[kh * 64 + qg * 16 + g + 8] = mhi;
        }
        __syncthreads();

        if (tid < 64) {
            float mo = mrow[tid];
            float mn = fmaxf(mo, fmaxf(pmax[tid], pmax[64 + tid]));
            srow[tid] = __expf(mo - mn);
            mrow[tid] = mn;
        }
        __syncthreads();   // Ks safe to overwrite with P

        // exp, write P (tf32) into Ks, partial sums
        const float mloN = mrow[qg * 16 + g];
        const float mhiN = mrow[qg * 16 + g + 8];
        float slo = 0.0f, shi = 0.0f;
        #pragma unroll
        for (int nt = 0; nt < 4; nt++) {
            const int col = kh * 32 + nt * 8 + 2 * tg;
            float p0 = __expf(s[nt][0] - mloN);
            float p1 = __expf(s[nt][1] - mloN);
            float p2 = __expf(s[nt][2] - mhiN);
            float p3 = __expf(s[nt][3] - mhiN);
            uint32_t* plo = Ks + (qg * 16 + g) * QP + col;
            uint32_t* phi = Ks + (qg * 16 + g + 8) * QP + col;
            plo[0] = tf32r(p0); plo[1] = tf32r(p1);
            phi[0] = tf32r(p2); phi[1] = tf32r(p3);
            slo += p0 + p1;
            shi += p2 + p3;
        }
        #pragma unroll
        for (int o = 1; o <= 2; o <<= 1) {
            slo += __shfl_xor_sync(0xffffffffu, slo, o);
            shi += __shfl_xor_sync(0xffffffffu, shi, o);
        }
        if (tg == 0) {
            psum[kh * 64 + qg * 16 + g]     = slo;
            psum[kh * 64 + qg * 16 + g + 8] = shi;
        }

        // rescale accumulators
        {
            const float sc0 = srow[qg * 16 + g];
            const float sc1 = srow[qg * 16 + g + 8];
            #pragma unroll
            for (int nt = 0; nt < 12; nt++) {
                oa[nt][0] *= sc0; oa[nt][1] *= sc0;
                oa[nt][2] *= sc1; oa[nt][3] *= sc1;
            }
        }
        __syncthreads();   // P + psum visible

        if (tid < 64)
            lrow[tid] = lrow[tid] * srow[tid] + psum[tid] + psum[64 + tid];

        // O += P @ V
        #pragma unroll
        for (int ks = 0; ks < 8; ks++) {
            const int k8 = ks * 8;
            uint32_t af[4];
            const uint32_t* ap = Ks + (qg * 16 + g) * QP + k8 + tg;
            af[0] = ap[0];
            af[1] = ap[8 * QP];
            af[2] = ap[4];
            af[3] = ap[8 * QP + 4];
            #pragma unroll
            for (int nt = 0; nt < 12; nt++) {
                const uint32_t* bp = Vs + (k8 + tg) * VP + kh * 96 + nt * 8 + g;
                uint32_t bf[2] = { bp[0], bp[4 * VP] };
                mma1688(oa[nt], af, bf);
            }
        }
    }

    __syncthreads();
    {
        const float ilo = 1.0f / lrow[qg * 16 + g];
        const float ihi = 1.0f / lrow[qg * 16 + g + 8];
        const size_t rlo = (size_t)(b * NSEQ + q0 + qg * 16 + g) * VW;
        const size_t rhi = rlo + 8 * VW;
        #pragma unroll
        for (int nt = 0; nt < 12; nt++) {
            const int col = h * DV + kh * 96 + nt * 8 + 2 * tg;
            // tf32-round so the O-projection GEMM loader is cvt-free
            uint2 v0 = { tf32r(oa[nt][0] * ilo), tf32r(oa[nt][1] * ilo) };
            uint2 v1 = { tf32r(oa[nt][2] * ihi), tf32r(oa[nt][3] * ihi) };
            *(uint2*)(out + rlo + col) = v0;
            *(uint2*)(out + rhi + col) = v1;
        }
    }
}

// ---------------------------------------------------------------------------
extern "C" void kernel_launch(void* const* d_in, const int* in_sizes, int n_in,
                              void* d_out, int out_size)
{
    (void)in_sizes; (void)n_in; (void)out_size;
    const float* x   = (const float*)d_in[0];
    const float* Wq  = (const float*)d_in[1];
    const float* Wk  = (const float*)d_in[2];
    const float* Wv  = (const float*)d_in[3];
    const float* Wo  = (const float*)d_in[4];
    const float* bo  = (const float*)d_in[5];
    const float* pos = (const float*)d_in[6];
    const float* rb  = (const float*)d_in[7];
    float* out = (float*)d_out;

    float *xt, *qkv, *ao, *wT, *woT, *u, *cvec;
    cudaGetSymbolAddress((void**)&xt,   g_xt);
    cudaGetSymbolAddress((void**)&qkv,  g_qkv);
    cudaGetSymbolAddress((void**)&ao,   g_ao);
    cudaGetSymbolAddress((void**)&wT,   g_wT);
    cudaGetSymbolAddress((void**)&woT,  g_woT);
    cudaGetSymbolAddress((void**)&u,    g_u);
    cudaGetSymbolAddress((void**)&cvec, g_c);

    const int attn_smem = (64 * QP * 2 + 64 * VP) * 4 + (64 * 4 + 128 * 2) * 4;
    cudaFuncSetAttribute(attn_mma, cudaFuncAttributeMaxDynamicSharedMemorySize, attn_smem);

    dim3 tb(32, 8);
    // prep: tf32 copies / transposes / exact bias route
    cvt_tf32<<<(MROWS * DIMM / 4 + 255) / 256, 256>>>(x, xt, MROWS * DIMM / 4);
    transpose_k<<<dim3(QKW / 32,  DIMM / 32), tb>>>(Wq, wT,                       DIMM, QKW);
    transpose_k<<<dim3(QKW / 32,  DIMM / 32), tb>>>(Wk, wT + (size_t)QKW * DIMM,  DIMM, QKW);
    transpose_k<<<dim3(VW  / 32,  DIMM / 32), tb>>>(Wv, wT + (size_t)2 * QKW * DIMM, DIMM, VW);
    transpose_k<<<dim3(DIMM / 32, VW  / 32),  tb>>>(Wo, woT, VW, DIMM);
    compute_u<<<(HEADS * DIMM + 255) / 256, 256>>>(Wk, rb, u);
    compute_c<<<MROWS / 256, 256>>>(x, u, cvec);

    // fused Q|K|V projection (k/v columns written tf32-rounded)
    gemm_mma<<<dim3(QKVW / 128, MROWS / 128), 256>>>(xt, wT, qkv, nullptr,
                                                     MROWS, QKVW, DIMM, QKW);
    // attention
    attn_mma<<<dim3(NSEQ / 64, HEADS, BATCH), 256, attn_smem>>>(qkv, pos, cvec, ao);
    // output projection + bias (no rounding)
    gemm_mma<<<dim3(DIMM / 128, MROWS / 128), 256>>>(ao, woT, out, bo,
                                                     MROWS, DIMM, VW, 1 << 30);
}

// round 17
// speedup vs baseline: 4.3869x; 1.8245x over previous
#include <cuda_runtime.h>
#include <cuda_fp16.h>
#include <cstdint>

#define BATCH 2
#define NSEQ  2048
#define DIMM  1536
#define HEADS 8
#define DK    64
#define DV    192
#define QSCALE 0.125f

#define MROWS (BATCH*NSEQ)          // 4096
#define QKW   (HEADS*DK)            // 512
#define VW    (HEADS*DV)            // 1536
#define QKVW  (2*QKW + VW)          // 2560 (q | k | v)

// ---- static device scratch (allocation-free) ----
__device__ __half g_xh [MROWS * DIMM];     // x as half
__device__ __half g_wh [QKVW * DIMM];      // [Wq|Wk|Wv]^T half (K-major)
__device__ __half g_qkv[MROWS * QKVW];     // fused projections (half)
__device__ __half g_ao [MROWS * VW];       // attn out (half)
__device__ __half g_woh[DIMM * VW];        // Wo^T half
__device__ float  g_u  [HEADS * DIMM];     // Wk_h @ relb_h
__device__ float  g_c  [HEADS * MROWS];    // exact relb.k (fp32)

// =========================== helpers ================================
__device__ __forceinline__ uint32_t sm_u32(const void* p) {
    uint32_t a;
    asm("{ .reg .u64 t; cvta.to.shared.u64 t, %1; cvt.u32.u64 %0, t; }" : "=r"(a) : "l"(p));
    return a;
}
__device__ __forceinline__ void mmah(float* d, const uint32_t* a, const uint32_t* b) {
    asm volatile(
        "mma.sync.aligned.m16n8k16.row.col.f32.f16.f16.f32 "
        "{%0,%1,%2,%3}, {%4,%5,%6,%7}, {%8,%9}, {%0,%1,%2,%3};"
        : "+f"(d[0]), "+f"(d[1]), "+f"(d[2]), "+f"(d[3])
        : "r"(a[0]), "r"(a[1]), "r"(a[2]), "r"(a[3]), "r"(b[0]), "r"(b[1]));
}
#define LDSM4(r0,r1,r2,r3,a) \
    asm volatile("ldmatrix.sync.aligned.m8n8.x4.shared.b16 {%0,%1,%2,%3}, [%4];" \
        : "=r"(r0),"=r"(r1),"=r"(r2),"=r"(r3) : "r"(a))
#define LDSM4T(r0,r1,r2,r3,a) \
    asm volatile("ldmatrix.sync.aligned.m8n8.x4.trans.shared.b16 {%0,%1,%2,%3}, [%4];" \
        : "=r"(r0),"=r"(r1),"=r"(r2),"=r"(r3) : "r"(a))
#define CPA(dst,src) asm volatile("cp.async.ca.shared.global [%0], [%1], 16;" :: "r"(dst), "l"(src))
#define CPC()  asm volatile("cp.async.commit_group;")
#define CPW1() asm volatile("cp.async.wait_group 1;")
#define CPW0() asm volatile("cp.async.wait_group 0;")

// ==================== prep kernels (once per launch) ========================
__global__ void cvt_h(const float* __restrict__ src, __half* __restrict__ dst, int n4)
{
    int i = blockIdx.x * 256 + threadIdx.x;
    if (i < n4) {
        float4 v = ((const float4*)src)[i];
        __half2 h0 = __floats2half2_rn(v.x, v.y);
        __half2 h1 = __floats2half2_rn(v.z, v.w);
        ((__half2*)dst)[2 * i]     = h0;
        ((__half2*)dst)[2 * i + 1] = h1;
    }
}

// transpose + half round: src [R, C] float -> dst [C, R] half
__global__ void transpose_h(const float* __restrict__ src, __half* __restrict__ dst,
                            int R, int C)
{
    __shared__ float t[32][33];
    const int c  = blockIdx.x * 32 + threadIdx.x;
    const int r0 = blockIdx.y * 32;
    #pragma unroll
    for (int j = threadIdx.y; j < 32; j += 8)
        t[j][threadIdx.x] = src[(size_t)(r0 + j) * C + c];
    __syncthreads();
    const int rr  = r0 + threadIdx.x;
    const int cc0 = blockIdx.x * 32;
    #pragma unroll
    for (int j = threadIdx.y; j < 32; j += 8)
        dst[(size_t)(cc0 + j) * R + rr] = __float2half(t[threadIdx.x][j]);
}

__global__ void compute_u(const float* __restrict__ Wk, const float* __restrict__ relb,
                          float* __restrict__ u)
{
    int t = blockIdx.x * 256 + threadIdx.x;
    if (t >= HEADS * DIMM) return;
    int h = t / DIMM, d = t % DIMM;
    float s = 0.0f;
    #pragma unroll 8
    for (int i = 0; i < DK; i++)
        s += Wk[(size_t)d * QKW + h * DK + i] * relb[h * DK + i];
    u[h * DIMM + d] = s;
}

__global__ __launch_bounds__(256)
void compute_c(const float* __restrict__ x, const float* __restrict__ u,
               float* __restrict__ c)
{
    __shared__ float us[HEADS * DIMM];   // 48 KB
    for (int i = threadIdx.x; i < HEADS * DIMM; i += 256)
        us[i] = u[i];
    __syncthreads();
    const int m = blockIdx.x * 256 + threadIdx.x;
    float acc[HEADS];
    #pragma unroll
    for (int h = 0; h < HEADS; h++) acc[h] = 0.0f;
    const float4* xr = (const float4*)(x + (size_t)m * DIMM);
    for (int d4 = 0; d4 < DIMM / 4; d4++) {
        float4 xv = xr[d4];
        #pragma unroll
        for (int h = 0; h < HEADS; h++) {
            float4 uv = *(const float4*)(us + h * DIMM + d4 * 4);
            acc[h] += xv.x * uv.x + xv.y * uv.y + xv.z * uv.z + xv.w * uv.w;
        }
    }
    #pragma unroll
    for (int h = 0; h < HEADS; h++) c[h * MROWS + m] = acc[h];
}

// ================ fp16 tensor-core GEMM (mma.m16n8k16) =====================
// C[M,Ntot] = A[M,K] @ Bt[Ntot,K]^T (+bias if float out).
// 128x128 tile, K-chunk 64, cp.async double-buffered, ldmatrix fragments.
// smem per stage: A 128x72 half (18432B) + B same -> 36864B; 2 stages = 73728B.
#define GSTG 36864u

template<int HALF_OUT>
__global__ __launch_bounds__(256)
void gemm_h(const __half* __restrict__ A, const __half* __restrict__ Bt,
            void* __restrict__ Cv, const float* __restrict__ bias,
            int M, int Ntot, int K)
{
    extern __shared__ __half gsm[];
    const int tid  = threadIdx.x;
    const int lane = tid & 31;
    const int g    = lane >> 2;
    const int tg   = lane & 3;
    const int wid  = tid >> 5;
    const int wr   = (wid & 1) * 64;
    const int wc   = (wid >> 1) * 32;
    const int brow = blockIdx.y * 128;
    const int bcol = blockIdx.x * 128;

    const __half* Ab = A  + (size_t)brow * K;
    const __half* Bb = Bt + (size_t)bcol * K;
    const int nch = K >> 6;

    const uint32_t smb = sm_u32(gsm);
    const int aRow = (lane & 7) + ((lane >> 3) & 1) * 8;
    const int aK   = (lane >> 4) * 8;
    const int bRow = (lane & 7) + (lane >> 4) * 8;
    const int bK   = ((lane >> 3) & 1) * 8;
    const int crow = tid >> 3;          // + l*32
    const int cc8  = tid & 7;

    float d[4][4][4];
    #pragma unroll
    for (int mt = 0; mt < 4; mt++)
        #pragma unroll
        for (int nt = 0; nt < 4; nt++)
            #pragma unroll
            for (int i = 0; i < 4; i++) d[mt][nt][i] = 0.0f;

    // issue stage 0
    #pragma unroll
    for (int l = 0; l < 4; l++) {
        int row = crow + l * 32;
        uint32_t da = smb + row * 144 + cc8 * 16;
        CPA(da,          Ab + (size_t)row * K + cc8 * 8);
        CPA(da + 18432u, Bb + (size_t)row * K + cc8 * 8);
    }
    CPC();

    for (int c = 0; c < nch; ++c) {
        const uint32_t sb = smb + (uint32_t)(c & 1) * GSTG;
        if (c + 1 < nch) {
            const uint32_t nb = smb + (uint32_t)((c + 1) & 1) * GSTG;
            const int k0 = (c + 1) << 6;
            #pragma unroll
            for (int l = 0; l < 4; l++) {
                int row = crow + l * 32;
                uint32_t da = nb + row * 144 + cc8 * 16;
                CPA(da,          Ab + (size_t)row * K + k0 + cc8 * 8);
                CPA(da + 18432u, Bb + (size_t)row * K + k0 + cc8 * 8);
            }
            CPC(); CPW1();
        } else {
            CPW0();
        }
        __syncthreads();

        const uint32_t aB = sb + ((wr + aRow) * 72 + aK) * 2;
        const uint32_t bB = sb + 18432u + ((wc + bRow) * 72 + bK) * 2;
        #pragma unroll
        for (int ks = 0; ks < 4; ks++) {
            uint32_t af[4][4], bf[4][2];
            #pragma unroll
            for (int mt = 0; mt < 4; mt++)
                LDSM4(af[mt][0], af[mt][1], af[mt][2], af[mt][3],
                      aB + mt * 2304 + ks * 32);
            LDSM4(bf[0][0], bf[0][1], bf[1][0], bf[1][1], bB + ks * 32);
            LDSM4(bf[2][0], bf[2][1], bf[3][0], bf[3][1], bB + 2304 + ks * 32);
            #pragma unroll
            for (int mt = 0; mt < 4; mt++)
                #pragma unroll
                for (int nt = 0; nt < 4; nt++)
                    mmah(d[mt][nt], af[mt], bf[nt]);
        }
        __syncthreads();
    }

    #pragma unroll
    for (int mt = 0; mt < 4; mt++) {
        const int row0 = brow + wr + mt * 16 + g;
        #pragma unroll
        for (int nt = 0; nt < 4; nt++) {
            const int col = bcol + wc + nt * 8 + 2 * tg;
            if (HALF_OUT) {
                __half* C = (__half*)Cv;
                *(__half2*)(C + (size_t)row0 * Ntot + col) =
                    __floats2half2_rn(d[mt][nt][0], d[mt][nt][1]);
                *(__half2*)(C + (size_t)(row0 + 8) * Ntot + col) =
                    __floats2half2_rn(d[mt][nt][2], d[mt][nt][3]);
            } else {
                float* C = (float*)Cv;
                float2 v0 = { d[mt][nt][0], d[mt][nt][1] };
                float2 v1 = { d[mt][nt][2], d[mt][nt][3] };
                if (bias) {
                    float2 bv = *(const float2*)(bias + col);
                    v0.x += bv.x; v0.y += bv.y;
                    v1.x += bv.x; v1.y += bv.y;
                }
                *(float2*)(C + (size_t)row0 * Ntot + col)       = v0;
                *(float2*)(C + (size_t)(row0 + 8) * Ntot + col) = v1;
            }
        }
    }
}

// ============== flash attention on fp16 tensor cores =======================
// logits = (q*s+pos).k [f16 mma] + c_j [exact fp32, precomputed].
#define QPH 72
#define VPH 200

__global__ __launch_bounds__(256, 2)
void attn_h(const __half* __restrict__ qkv, const float* __restrict__ pos,
            const float* __restrict__ cvec, __half* __restrict__ out)
{
    extern __shared__ __half smh[];
    __half* Qs = smh;                    // 64 x QPH
    __half* Ks = Qs + 64 * QPH;          // K tile, reused as P tile
    __half* Vs = Ks + 64 * QPH;          // 64 x VPH
    float* cs   = (float*)(Vs + 64 * VPH);   // 64
    float* mrow = cs + 64;
    float* lrow = mrow + 64;
    float* srow = lrow + 64;
    float* pmax = srow + 64;             // 2 x 64
    float* psum = pmax + 128;            // 2 x 64

    const int tid  = threadIdx.x;
    const int lane = tid & 31;
    const int g    = lane >> 2;
    const int tg   = lane & 3;
    const int wid  = tid >> 5;
    const int qg   = wid & 3;
    const int kh   = wid >> 2;
    const int b    = blockIdx.z, h = blockIdx.y;
    const int q0   = blockIdx.x * 64;

    const __half* qb = qkv + (size_t)b * NSEQ * QKVW + h * DK;
    const __half* kb = qb + QKW;
    const __half* vb = qkv + (size_t)b * NSEQ * QKVW + 2 * QKW + h * DV;
    const float* pb = pos + (size_t)h * NSEQ * DK;
    const float* cb = cvec + h * MROWS + b * NSEQ;

    const int aRow = (lane & 7) + ((lane >> 3) & 1) * 8;
    const int aK   = (lane >> 4) * 8;
    const int bRow = (lane & 7) + (lane >> 4) * 8;
    const int bK   = ((lane >> 3) & 1) * 8;
    const uint32_t smb = sm_u32(smh);
    const uint32_t qA = smb + ((qg * 16 + aRow) * QPH + aK) * 2;
    const uint32_t kB = smb + 64 * QPH * 2 + ((kh * 32 + bRow) * QPH + bK) * 2;
    const uint32_t pA = smb + 64 * QPH * 2 + ((qg * 16 + aRow) * QPH + aK) * 2;
    const uint32_t vB = smb + 128 * QPH * 2 + (aRow * VPH + kh * 96 + aK) * 2;

    // Q tile: (q*scale + pos) -> half
    #pragma unroll
    for (int l = 0; l < 2; l++) {
        int e = tid + l * 256;
        int r = e >> 3, c8 = e & 7;
        uint4 qv = *(const uint4*)(qb + (size_t)(q0 + r) * QKVW + c8 * 8);
        const __half2* qh = (const __half2*)&qv;
        float4 p0 = *(const float4*)(pb + (size_t)(q0 + r) * DK + c8 * 8);
        float4 p1 = *(const float4*)(pb + (size_t)(q0 + r) * DK + c8 * 8 + 4);
        float2 f0 = __half22float2(qh[0]);
        float2 f1 = __half22float2(qh[1]);
        float2 f2 = __half22float2(qh[2]);
        float2 f3 = __half22float2(qh[3]);
        __half2 o[4];
        o[0] = __floats2half2_rn(f0.x * QSCALE + p0.x, f0.y * QSCALE + p0.y);
        o[1] = __floats2half2_rn(f1.x * QSCALE + p0.z, f1.y * QSCALE + p0.w);
        o[2] = __floats2half2_rn(f2.x * QSCALE + p1.x, f2.y * QSCALE + p1.y);
        o[3] = __floats2half2_rn(f3.x * QSCALE + p1.z, f3.y * QSCALE + p1.w);
        *(uint4*)(Qs + r * QPH + c8 * 8) = *(uint4*)o;
    }
    if (tid < 64) { mrow[tid] = -1e30f; lrow[tid] = 0.0f; }

    float oa[12][4];
    #pragma unroll
    for (int nt = 0; nt < 12; nt++)
        #pragma unroll
        for (int i = 0; i < 4; i++) oa[nt][i] = 0.0f;

    for (int j0 = 0; j0 < NSEQ; j0 += 64) {
        __syncthreads();   // previous P/V fully consumed

        // K tile — raw half copy
        #pragma unroll
        for (int l = 0; l < 2; l++) {
            int e = tid + l * 256;
            int r = e >> 3, c8 = e & 7;
            *(uint4*)(Ks + r * QPH + c8 * 8) =
                *(const uint4*)(kb + (size_t)(j0 + r) * QKVW + c8 * 8);
        }
        // V tile — raw half copy
        #pragma unroll
        for (int l = 0; l < 6; l++) {
            int e = tid + l * 256;
            int r = e / 24, c8 = e % 24;
            *(uint4*)(Vs + r * VPH + c8 * 8) =
                *(const uint4*)(vb + (size_t)(j0 + r) * QKVW + c8 * 8);
        }
        if (tid < 64) cs[tid] = cb[j0 + tid];
        __syncthreads();

        // S = Qb @ K^T : warp -> 16 q rows x 32 keys (4 n-tiles)
        float s[4][4];
        #pragma unroll
        for (int nt = 0; nt < 4; nt++)
            #pragma unroll
            for (int i = 0; i < 4; i++) s[nt][i] = 0.0f;
        #pragma unroll
        for (int ks = 0; ks < 4; ks++) {
            uint32_t af[4], bf[4][2];
            LDSM4(af[0], af[1], af[2], af[3], qA + ks * 32);
            LDSM4(bf[0][0], bf[0][1], bf[1][0], bf[1][1], kB + ks * 32);
            LDSM4(bf[2][0], bf[2][1], bf[3][0], bf[3][1], kB + 16 * QPH * 2 + ks * 32);
            #pragma unroll
            for (int nt = 0; nt < 4; nt++)
                mmah(s[nt], af, bf[nt]);
        }
        // exact rank-1 bias term
        #pragma unroll
        for (int nt = 0; nt < 4; nt++) {
            const int col0 = kh * 32 + nt * 8 + 2 * tg;
            float c0 = cs[col0], c1 = cs[col0 + 1];
            s[nt][0] += c0; s[nt][1] += c1;
            s[nt][2] += c0; s[nt][3] += c1;
        }

        // row max
        float mlo = -1e30f, mhi = -1e30f;
        #pragma unroll
        for (int nt = 0; nt < 4; nt++) {
            mlo = fmaxf(mlo, fmaxf(s[nt][0], s[nt][1]));
            mhi = fmaxf(mhi, fmaxf(s[nt][2], s[nt][3]));
        }
        #pragma unroll
        for (int o = 1; o <= 2; o <<= 1) {
            mlo = fmaxf(mlo, __shfl_xor_sync(0xffffffffu, mlo, o));
            mhi = fmaxf(mhi, __shfl_xor_sync(0xffffffffu, mhi, o));
        }
        if (tg == 0) {
            pmax[kh * 64 + qg * 16 + g]     = mlo;
            pmax[kh * 64 + qg * 16 + g + 8] = mhi;
        }
        __syncthreads();

        if (tid < 64) {
            float mo = mrow[tid];
            float mn = fmaxf(mo, fmaxf(pmax[tid], pmax[64 + tid]));
            srow[tid] = __expf(mo - mn);
            mrow[tid] = mn;
        }
        __syncthreads();   // Ks safe to overwrite with P

        // exp, write P (half) into Ks, partial sums
        const float mloN = mrow[qg * 16 + g];
        const float mhiN = mrow[qg * 16 + g + 8];
        float slo = 0.0f, shi = 0.0f;
        #pragma unroll
        for (int nt = 0; nt < 4; nt++) {
            const int col = kh * 32 + nt * 8 + 2 * tg;
            float p0 = __expf(s[nt][0] - mloN);
            float p1 = __expf(s[nt][1] - mloN);
            float p2 = __expf(s[nt][2] - mhiN);
            float p3 = __expf(s[nt][3] - mhiN);
            *(__half2*)(Ks + (qg * 16 + g) * QPH + col)     = __floats2half2_rn(p0, p1);
            *(__half2*)(Ks + (qg * 16 + g + 8) * QPH + col) = __floats2half2_rn(p2, p3);
            slo += p0 + p1;
            shi += p2 + p3;
        }
        #pragma unroll
        for (int o = 1; o <= 2; o <<= 1) {
            slo += __shfl_xor_sync(0xffffffffu, slo, o);
            shi += __shfl_xor_sync(0xffffffffu, shi, o);
        }
        if (tg == 0) {
            psum[kh * 64 + qg * 16 + g]     = slo;
            psum[kh * 64 + qg * 16 + g + 8] = shi;
        }

        // rescale accumulators
        {
            const float sc0 = srow[qg * 16 + g];
            const float sc1 = srow[qg * 16 + g + 8];
            #pragma unroll
            for (int nt = 0; nt < 12; nt++) {
                oa[nt][0] *= sc0; oa[nt][1] *= sc0;
                oa[nt][2] *= sc1; oa[nt][3] *= sc1;
            }
        }
        __syncthreads();   // P + psum visible

        if (tid < 64)
            lrow[tid] = lrow[tid] * srow[tid] + psum[tid] + psum[64 + tid];

        // O += P @ V : warp -> 16 q rows x 96 dv cols (kh half), V via ldmatrix.trans
        #pragma unroll
        for (int ks = 0; ks < 4; ks++) {
            uint32_t af[4];
            LDSM4(af[0], af[1], af[2], af[3], pA + ks * 32);
            const uint32_t vBk = vB + ks * 16 * VPH * 2;
            #pragma unroll
            for (int np = 0; np < 6; np++) {
                uint32_t bf[2][2];
                LDSM4T(bf[0][0], bf[0][1], bf[1][0], bf[1][1], vBk + np * 32);
                mmah(oa[2 * np],     af, bf[0]);
                mmah(oa[2 * np + 1], af, bf[1]);
            }
        }
    }

    __syncthreads();
    {
        const float ilo = 1.0f / lrow[qg * 16 + g];
        const float ihi = 1.0f / lrow[qg * 16 + g + 8];
        const size_t rlo = (size_t)(b * NSEQ + q0 + qg * 16 + g) * VW;
        const size_t rhi = rlo + 8 * VW;
        #pragma unroll
        for (int nt = 0; nt < 12; nt++) {
            const int col = h * DV + kh * 96 + nt * 8 + 2 * tg;
            *(__half2*)(out + rlo + col) =
                __floats2half2_rn(oa[nt][0] * ilo, oa[nt][1] * ilo);
            *(__half2*)(out + rhi + col) =
                __floats2half2_rn(oa[nt][2] * ihi, oa[nt][3] * ihi);
        }
    }
}

// ---------------------------------------------------------------------------
extern "C" void kernel_launch(void* const* d_in, const int* in_sizes, int n_in,
                              void* d_out, int out_size)
{
    (void)in_sizes; (void)n_in; (void)out_size;
    const float* x   = (const float*)d_in[0];
    const float* Wq  = (const float*)d_in[1];
    const float* Wk  = (const float*)d_in[2];
    const float* Wv  = (const float*)d_in[3];
    const float* Wo  = (const float*)d_in[4];
    const float* bo  = (const float*)d_in[5];
    const float* pos = (const float*)d_in[6];
    const float* rb  = (const float*)d_in[7];
    float* out = (float*)d_out;

    __half *xh, *wh, *qkv, *ao, *woh;
    float *u, *cvec;
    cudaGetSymbolAddress((void**)&xh,   g_xh);
    cudaGetSymbolAddress((void**)&wh,   g_wh);
    cudaGetSymbolAddress((void**)&qkv,  g_qkv);
    cudaGetSymbolAddress((void**)&ao,   g_ao);
    cudaGetSymbolAddress((void**)&woh,  g_woh);
    cudaGetSymbolAddress((void**)&u,    g_u);
    cudaGetSymbolAddress((void**)&cvec, g_c);

    const int attn_smem = (128 * QPH + 64 * VPH) * 2 + (64 * 4 + 128 * 2) * 4;
    const int gemm_smem = 2 * GSTG;   // 73728
    cudaFuncSetAttribute(attn_h,    cudaFuncAttributeMaxDynamicSharedMemorySize, attn_smem);
    cudaFuncSetAttribute(gemm_h<0>, cudaFuncAttributeMaxDynamicSharedMemorySize, gemm_smem);
    cudaFuncSetAttribute(gemm_h<1>, cudaFuncAttributeMaxDynamicSharedMemorySize, gemm_smem);

    dim3 tb(32, 8);
    cvt_h<<<(MROWS * DIMM / 4 + 255) / 256, 256>>>(x, xh, MROWS * DIMM / 4);
    transpose_h<<<dim3(QKW / 32,  DIMM / 32), tb>>>(Wq, wh,                          DIMM, QKW);
    transpose_h<<<dim3(QKW / 32,  DIMM / 32), tb>>>(Wk, wh + (size_t)QKW * DIMM,     DIMM, QKW);
    transpose_h<<<dim3(VW  / 32,  DIMM / 32), tb>>>(Wv, wh + (size_t)2 * QKW * DIMM, DIMM, VW);
    transpose_h<<<dim3(DIMM / 32, VW  / 32),  tb>>>(Wo, woh, VW, DIMM);
    compute_u<<<(HEADS * DIMM + 255) / 256, 256>>>(Wk, rb, u);
    compute_c<<<MROWS / 256, 256>>>(x, u, cvec);

    // fused Q|K|V projection (half out)
    gemm_h<1><<<dim3(QKVW / 128, MROWS / 128), 256, gemm_smem>>>(
        xh, wh, qkv, nullptr, MROWS, QKVW, DIMM);
    // attention (half out)
    attn_h<<<dim3(NSEQ / 64, HEADS, BATCH), 256, attn_smem>>>(qkv, pos, cvec, ao);
    // output projection + bias (float out)
    gemm_h<0><<<dim3(DIMM / 128, MROWS / 128), 256, gemm_smem>>>(
        ao, woh, out, bo, MROWS, DIMM, VW);
}